// round 2
// baseline (speedup 1.0000x reference)
#include <cuda_runtime.h>
#include <math.h>

#define D_MODEL   1024
#define N_HEADS   16
#define HEAD_DIM  64
#define SEQ_L     2048
#define BATCH     2
#define NTOK      (BATCH * SEQ_L)      // 4096
#define HALF_WIN  128                  // WINDOW//2
#define LN_EPS    1e-5f

// ---------------- scratch (no allocation allowed) ----------------
__device__ float g_h  [NTOK * D_MODEL];      // LN1 output
__device__ float g_qkv[NTOK * 3 * D_MODEL];  // qkv projection
__device__ float g_att[NTOK * D_MODEL];      // attention output (token-major)
__device__ float g_x1 [NTOK * D_MODEL];      // x + attn_out
__device__ float g_h2 [NTOK * D_MODEL];      // LN2 output
__device__ float g_ff [NTOK * 2 * D_MODEL];  // gelu(ffn1)

// ---------------- helpers ----------------
__inline__ __device__ float warp_sum(float v) {
    #pragma unroll
    for (int o = 16; o > 0; o >>= 1) v += __shfl_xor_sync(0xffffffffu, v, o);
    return v;
}
__inline__ __device__ float warp_max(float v) {
    #pragma unroll
    for (int o = 16; o > 0; o >>= 1) v = fmaxf(v, __shfl_xor_sync(0xffffffffu, v, o));
    return v;
}

// ---------------- LayerNorm: one block per token ----------------
__global__ void __launch_bounds__(256)
ln_kernel(const float* __restrict__ x, const float* __restrict__ g,
          const float* __restrict__ b, float* __restrict__ out)
{
    int row = blockIdx.x;
    const float* xr = x + (size_t)row * D_MODEL;
    float*       orow = out + (size_t)row * D_MODEL;
    int tid = threadIdx.x;

    float v[4];
    float s = 0.f, ss = 0.f;
    #pragma unroll
    for (int i = 0; i < 4; i++) {
        v[i] = xr[tid + i * 256];
        s  += v[i];
        ss += v[i] * v[i];
    }
    __shared__ float shs[8], shss[8], fin[2];
    int lane = tid & 31, warp = tid >> 5;
    s = warp_sum(s); ss = warp_sum(ss);
    if (lane == 0) { shs[warp] = s; shss[warp] = ss; }
    __syncthreads();
    if (tid == 0) {
        float a = 0.f, c = 0.f;
        #pragma unroll
        for (int i = 0; i < 8; i++) { a += shs[i]; c += shss[i]; }
        fin[0] = a; fin[1] = c;
    }
    __syncthreads();
    float mu  = fin[0] * (1.f / D_MODEL);
    float var = fin[1] * (1.f / D_MODEL) - mu * mu;
    float inv = rsqrtf(var + LN_EPS);
    #pragma unroll
    for (int i = 0; i < 4; i++) {
        int c = tid + i * 256;
        orow[c] = (v[i] - mu) * inv * g[c] + b[c];
    }
}

// ---------------- GEMM: C[M,N] = A[M,K] @ B[K,N] + bias (+res / gelu) ----------------
// 128x128 block tile, BK=8, 256 threads, 8x8 per thread. All dims multiples of tile.
#define EPI_BIAS     0
#define EPI_BIAS_RES 1
#define EPI_GELU     2

__global__ void __launch_bounds__(256)
gemm_kernel(const float* __restrict__ A, const float* __restrict__ Bm,
            const float* __restrict__ bias, const float* __restrict__ res,
            float* __restrict__ C, int M, int N, int K, int epi)
{
    __shared__ float As[8][128];
    __shared__ float Bs[8][128];

    int tid = threadIdx.x;
    int bm = blockIdx.y * 128;
    int bn = blockIdx.x * 128;

    int arow = tid >> 1;            // 0..127
    int acol = (tid & 1) * 4;       // 0 or 4
    int brow = tid >> 5;            // 0..7
    int bcol = (tid & 31) * 4;      // 0..124

    int tx = tid & 15, ty = tid >> 4;

    float acc[8][8];
    #pragma unroll
    for (int i = 0; i < 8; i++)
        #pragma unroll
        for (int j = 0; j < 8; j++) acc[i][j] = 0.f;

    const float* Aptr = A + (size_t)(bm + arow) * K + acol;
    const float* Bptr = Bm + (size_t)brow * N + bn + bcol;

    for (int k0 = 0; k0 < K; k0 += 8) {
        float4 a4 = *(const float4*)(Aptr + k0);
        As[acol + 0][arow] = a4.x;
        As[acol + 1][arow] = a4.y;
        As[acol + 2][arow] = a4.z;
        As[acol + 3][arow] = a4.w;
        float4 b4 = *(const float4*)(Bptr + (size_t)k0 * N);
        *(float4*)&Bs[brow][bcol] = b4;
        __syncthreads();

        #pragma unroll
        for (int k = 0; k < 8; ++k) {
            float ra[8], rb[8];
            float4 t0 = *(float4*)&As[k][ty * 8];
            float4 t1 = *(float4*)&As[k][ty * 8 + 4];
            ra[0]=t0.x; ra[1]=t0.y; ra[2]=t0.z; ra[3]=t0.w;
            ra[4]=t1.x; ra[5]=t1.y; ra[6]=t1.z; ra[7]=t1.w;
            float4 u0 = *(float4*)&Bs[k][tx * 8];
            float4 u1 = *(float4*)&Bs[k][tx * 8 + 4];
            rb[0]=u0.x; rb[1]=u0.y; rb[2]=u0.z; rb[3]=u0.w;
            rb[4]=u1.x; rb[5]=u1.y; rb[6]=u1.z; rb[7]=u1.w;
            #pragma unroll
            for (int i = 0; i < 8; i++)
                #pragma unroll
                for (int j = 0; j < 8; j++)
                    acc[i][j] = fmaf(ra[i], rb[j], acc[i][j]);
        }
        __syncthreads();
    }

    #pragma unroll
    for (int i = 0; i < 8; i++) {
        int r = bm + ty * 8 + i;
        float* crow = C + (size_t)r * N;
        const float* rrow = res ? res + (size_t)r * N : nullptr;
        #pragma unroll
        for (int j = 0; j < 8; j++) {
            int c = bn + tx * 8 + j;
            float v = acc[i][j] + bias[c];
            if (epi == EPI_BIAS_RES) {
                v += rrow[c];
            } else if (epi == EPI_GELU) {
                v = 0.5f * v * (1.0f + erff(v * 0.70710678118654752f));
            }
            crow[c] = v;
        }
    }
}

// ---------------- windowed attention ----------------
// grid (L/64, H, B), 256 threads. Key range per 64-query tile is always a
// multiple of 64 (q0 mult of 64, window 128 each side, L mult of 64).
#define SW 324   // padded score row width (max keys = 320)

__global__ void __launch_bounds__(256)
attn_kernel(const float* __restrict__ qkv, float* __restrict__ attn)
{
    int qt = blockIdx.x;
    int h  = blockIdx.y;
    int b  = blockIdx.z;
    int q0 = qt * 64;
    int jstart = max(0, q0 - HALF_WIN);
    int jend1  = min(SEQ_L, q0 + 64 + HALF_WIN);
    int nk = jend1 - jstart;
    int ntiles = nk >> 6;

    extern __shared__ float sm[];
    float* Qs = sm;                  // [64][65]
    float* Ks = Qs + 64 * 65;        // [64][65]
    float* Vs = Ks + 64 * 65;        // [64][65]
    float* Ss = Vs + 64 * 65;        // [64][SW]

    int tid = threadIdx.x;
    int tx = tid & 15, ty = tid >> 4;

    // load Q tile, pre-scaled by 1/sqrt(hd)
    {
        const float* qbase = qkv + ((size_t)(b * SEQ_L + q0)) * 3072 + h * 64;
        for (int idx = tid; idx < 64 * 64; idx += 256) {
            int r = idx >> 6, c = idx & 63;
            Qs[r * 65 + c] = qbase[(size_t)r * 3072 + c] * 0.125f;
        }
    }

    // ---- scores ----
    for (int t = 0; t < ntiles; ++t) {
        int jb = jstart + t * 64;
        const float* kbase = qkv + ((size_t)(b * SEQ_L + jb)) * 3072 + 1024 + h * 64;
        __syncthreads();
        for (int idx = tid; idx < 64 * 64; idx += 256) {
            int r = idx >> 6, c = idx & 63;
            Ks[r * 65 + c] = kbase[(size_t)r * 3072 + c];
        }
        __syncthreads();

        float acc[4][4];
        #pragma unroll
        for (int i = 0; i < 4; i++)
            #pragma unroll
            for (int j = 0; j < 4; j++) acc[i][j] = 0.f;

        #pragma unroll 4
        for (int d = 0; d < 64; ++d) {
            float qv[4], kv[4];
            #pragma unroll
            for (int i = 0; i < 4; i++) qv[i] = Qs[(ty * 4 + i) * 65 + d];
            #pragma unroll
            for (int j = 0; j < 4; j++) kv[j] = Ks[(tx * 4 + j) * 65 + d];
            #pragma unroll
            for (int i = 0; i < 4; i++)
                #pragma unroll
                for (int j = 0; j < 4; j++)
                    acc[i][j] = fmaf(qv[i], kv[j], acc[i][j]);
        }

        #pragma unroll
        for (int i = 0; i < 4; i++) {
            int qi = q0 + ty * 4 + i;
            #pragma unroll
            for (int j = 0; j < 4; j++) {
                int jg = jb + tx * 4 + j;
                int dd = jg - qi;
                float s = (dd >= -HALF_WIN && dd <= HALF_WIN) ? acc[i][j] : -INFINITY;
                Ss[(ty * 4 + i) * SW + t * 64 + tx * 4 + j] = s;
            }
        }
    }
    __syncthreads();

    // ---- softmax per row ----
    {
        int warp = tid >> 5, lane = tid & 31;
        for (int r = warp; r < 64; r += 8) {
            float* row = Ss + r * SW;
            float m = -INFINITY;
            for (int c = lane; c < nk; c += 32) m = fmaxf(m, row[c]);
            m = warp_max(m);
            float ssum = 0.f;
            for (int c = lane; c < nk; c += 32) {
                float e = expf(row[c] - m);
                row[c] = e;
                ssum += e;
            }
            ssum = warp_sum(ssum);
            float inv = 1.f / ssum;
            for (int c = lane; c < nk; c += 32) row[c] *= inv;
        }
    }

    // ---- O = P @ V ----
    float oacc[4][4];
    #pragma unroll
    for (int i = 0; i < 4; i++)
        #pragma unroll
        for (int j = 0; j < 4; j++) oacc[i][j] = 0.f;

    for (int t = 0; t < ntiles; ++t) {
        int jb = jstart + t * 64;
        const float* vbase = qkv + ((size_t)(b * SEQ_L + jb)) * 3072 + 2048 + h * 64;
        __syncthreads();
        for (int idx = tid; idx < 64 * 64; idx += 256) {
            int r = idx >> 6, c = idx & 63;
            Vs[r * 65 + c] = vbase[(size_t)r * 3072 + c];
        }
        __syncthreads();

        #pragma unroll 4
        for (int jj = 0; jj < 64; ++jj) {
            float pv[4], vv[4];
            #pragma unroll
            for (int i = 0; i < 4; i++) pv[i] = Ss[(ty * 4 + i) * SW + t * 64 + jj];
            #pragma unroll
            for (int j = 0; j < 4; j++) vv[j] = Vs[jj * 65 + tx * 4 + j];
            #pragma unroll
            for (int i = 0; i < 4; i++)
                #pragma unroll
                for (int j = 0; j < 4; j++)
                    oacc[i][j] = fmaf(pv[i], vv[j], oacc[i][j]);
        }
    }

    #pragma unroll
    for (int i = 0; i < 4; i++) {
        size_t rbase = ((size_t)(b * SEQ_L + q0 + ty * 4 + i)) * D_MODEL + h * 64 + tx * 4;
        #pragma unroll
        for (int j = 0; j < 4; j++)
            attn[rbase + j] = oacc[i][j];
    }
}

// ---------------- launch ----------------
extern "C" void kernel_launch(void* const* d_in, const int* in_sizes, int n_in,
                              void* d_out, int out_size)
{
    const float* x      = (const float*)d_in[0];
    const float* qkv_w  = (const float*)d_in[1];
    const float* qkv_b  = (const float*)d_in[2];
    const float* out_w  = (const float*)d_in[3];
    const float* out_b  = (const float*)d_in[4];
    const float* ln1_g  = (const float*)d_in[5];
    const float* ln1_b  = (const float*)d_in[6];
    const float* ln2_g  = (const float*)d_in[7];
    const float* ln2_b  = (const float*)d_in[8];
    const float* ffn_w1 = (const float*)d_in[9];
    const float* ffn_b1 = (const float*)d_in[10];
    const float* ffn_w2 = (const float*)d_in[11];
    const float* ffn_b2 = (const float*)d_in[12];
    float* out = (float*)d_out;

    float *h, *qkv, *att, *x1, *h2, *ff;
    cudaGetSymbolAddress((void**)&h,   g_h);
    cudaGetSymbolAddress((void**)&qkv, g_qkv);
    cudaGetSymbolAddress((void**)&att, g_att);
    cudaGetSymbolAddress((void**)&x1,  g_x1);
    cudaGetSymbolAddress((void**)&h2,  g_h2);
    cudaGetSymbolAddress((void**)&ff,  g_ff);

    int attn_smem = (3 * 64 * 65 + 64 * SW) * (int)sizeof(float);
    cudaFuncSetAttribute(attn_kernel, cudaFuncAttributeMaxDynamicSharedMemorySize, attn_smem);

    // 1) LN1
    ln_kernel<<<NTOK, 256>>>(x, ln1_g, ln1_b, h);
    // 2) QKV projection
    gemm_kernel<<<dim3(3 * D_MODEL / 128, NTOK / 128), 256>>>(
        h, qkv_w, qkv_b, nullptr, qkv, NTOK, 3 * D_MODEL, D_MODEL, EPI_BIAS);
    // 3) windowed attention
    attn_kernel<<<dim3(SEQ_L / 64, N_HEADS, BATCH), 256, attn_smem>>>(qkv, att);
    // 4) output projection + residual
    gemm_kernel<<<dim3(D_MODEL / 128, NTOK / 128), 256>>>(
        att, out_w, out_b, x, x1, NTOK, D_MODEL, D_MODEL, EPI_BIAS_RES);
    // 5) LN2
    ln_kernel<<<NTOK, 256>>>(x1, ln2_g, ln2_b, h2);
    // 6) FFN1 + GELU
    gemm_kernel<<<dim3(2 * D_MODEL / 128, NTOK / 128), 256>>>(
        h2, ffn_w1, ffn_b1, nullptr, ff, NTOK, 2 * D_MODEL, D_MODEL, EPI_GELU);
    // 7) FFN2 + residual -> out
    gemm_kernel<<<dim3(D_MODEL / 128, NTOK / 128), 256>>>(
        ff, ffn_w2, ffn_b2, x1, out, NTOK, D_MODEL, 2 * D_MODEL, EPI_BIAS_RES);
}

// round 3
// speedup vs baseline: 2.7270x; 2.7270x over previous
#include <cuda_runtime.h>
#include <math.h>
#include <stdint.h>

#define D_MODEL   1024
#define N_HEADS   16
#define HEAD_DIM  64
#define SEQ_L     2048
#define BATCH     2
#define NTOK      (BATCH * SEQ_L)      // 4096
#define HALF_WIN  128                  // WINDOW//2
#define LN_EPS    1e-5f

// ---------------- scratch (no allocation allowed) ----------------
__device__ float g_h  [NTOK * D_MODEL];      // LN1 output
__device__ float g_qkv[NTOK * 3 * D_MODEL];  // qkv projection
__device__ float g_att[NTOK * D_MODEL];      // attention output (token-major)
__device__ float g_x1 [NTOK * D_MODEL];      // x + attn_out
__device__ float g_h2 [NTOK * D_MODEL];      // LN2 output
__device__ float g_ff [NTOK * 2 * D_MODEL];  // gelu(ffn1)

// ---------------- helpers ----------------
__inline__ __device__ float warp_sum(float v) {
    #pragma unroll
    for (int o = 16; o > 0; o >>= 1) v += __shfl_xor_sync(0xffffffffu, v, o);
    return v;
}
__inline__ __device__ float warp_max(float v) {
    #pragma unroll
    for (int o = 16; o > 0; o >>= 1) v = fmaxf(v, __shfl_xor_sync(0xffffffffu, v, o));
    return v;
}

// ---------------- LayerNorm: one block per token ----------------
__global__ void __launch_bounds__(256)
ln_kernel(const float* __restrict__ x, const float* __restrict__ g,
          const float* __restrict__ b, float* __restrict__ out)
{
    int row = blockIdx.x;
    const float* xr = x + (size_t)row * D_MODEL;
    float*       orow = out + (size_t)row * D_MODEL;
    int tid = threadIdx.x;

    float v[4];
    float s = 0.f, ss = 0.f;
    #pragma unroll
    for (int i = 0; i < 4; i++) {
        v[i] = xr[tid + i * 256];
        s  += v[i];
        ss += v[i] * v[i];
    }
    __shared__ float shs[8], shss[8], fin[2];
    int lane = tid & 31, warp = tid >> 5;
    s = warp_sum(s); ss = warp_sum(ss);
    if (lane == 0) { shs[warp] = s; shss[warp] = ss; }
    __syncthreads();
    if (tid == 0) {
        float a = 0.f, c = 0.f;
        #pragma unroll
        for (int i = 0; i < 8; i++) { a += shs[i]; c += shss[i]; }
        fin[0] = a; fin[1] = c;
    }
    __syncthreads();
    float mu  = fin[0] * (1.f / D_MODEL);
    float var = fin[1] * (1.f / D_MODEL) - mu * mu;
    float inv = rsqrtf(var + LN_EPS);
    #pragma unroll
    for (int i = 0; i < 4; i++) {
        int c = tid + i * 256;
        orow[c] = (v[i] - mu) * inv * g[c] + b[c];
    }
}

// =================================================================
//  tf32 tensor-core GEMM: C[M,N] = A[M,K] @ B[K,N] + bias (+res / gelu)
//  128x128 block tile, BK=32, 8 warps (4x2), warp tile 32x64,
//  mma.sync.m16n8k8.tf32, cp.async double-buffered SMEM.
// =================================================================
#define EPI_BIAS     0
#define EPI_BIAS_RES 1
#define EPI_GELU     2

#define AP 36    // A smem row pitch (floats):  reads (4h+g)%32 conflict-free
#define NP 136   // B smem row pitch (floats):  reads (8g+h)%32 conflict-free
#define ASZ (128 * AP)   // 4608 floats per A buffer
#define BSZ (32  * NP)   // 4352 floats per B buffer
#define GEMM_SMEM ((2 * (ASZ + BSZ)) * sizeof(float))   // 71680 B

__device__ __forceinline__ void cp16(void* smem_dst, const void* gmem_src) {
    uint32_t s = (uint32_t)__cvta_generic_to_shared(smem_dst);
    asm volatile("cp.async.cg.shared.global [%0], [%1], 16;\n" :: "r"(s), "l"(gmem_src));
}
__device__ __forceinline__ void cp_commit() { asm volatile("cp.async.commit_group;\n"); }
__device__ __forceinline__ void cp_wait0()  { asm volatile("cp.async.wait_group 0;\n"); }

__device__ __forceinline__ void mma_tf32(float* c, const uint32_t* a, const uint32_t* b) {
    asm volatile(
        "mma.sync.aligned.m16n8k8.row.col.f32.tf32.tf32.f32 "
        "{%0,%1,%2,%3}, {%4,%5,%6,%7}, {%8,%9}, {%0,%1,%2,%3};\n"
        : "+f"(c[0]), "+f"(c[1]), "+f"(c[2]), "+f"(c[3])
        : "r"(a[0]), "r"(a[1]), "r"(a[2]), "r"(a[3]), "r"(b[0]), "r"(b[1]));
}

__global__ void __launch_bounds__(256)
gemm_tc_kernel(const float* __restrict__ A, const float* __restrict__ Bm,
               const float* __restrict__ bias, const float* __restrict__ res,
               float* __restrict__ C, int M, int N, int K, int epi)
{
    extern __shared__ float smem[];
    float* As = smem;              // [2][128][AP]
    float* Bs = smem + 2 * ASZ;    // [2][32][NP]

    int tid  = threadIdx.x;
    int lane = tid & 31;
    int warp = tid >> 5;
    int warp_m = (warp & 3) * 32;   // 4 warps down M
    int warp_n = (warp >> 2) * 64;  // 2 warps across N
    int bm = blockIdx.y * 128;
    int bn = blockIdx.x * 128;

    // gmem->smem mapping (per thread: 4 float4 for A, 4 float4 for B)
    // A tile 128x32: idx over 1024 float4: m = idx>>3, k4 = (idx&7)*4
    // B tile 32x128: idx over 1024 float4: k = idx>>5, n4 = (idx&31)*4
    const int kIters = K >> 5;

    auto load_tile = [&](int it, int buf) {
        int k0 = it << 5;
        float* Ab = As + buf * ASZ;
        float* Bb = Bs + buf * BSZ;
        #pragma unroll
        for (int t = 0; t < 4; t++) {
            int idx = tid + t * 256;
            int m  = idx >> 3;
            int k4 = (idx & 7) << 2;
            cp16(Ab + m * AP + k4, A + (size_t)(bm + m) * K + k0 + k4);
        }
        #pragma unroll
        for (int t = 0; t < 4; t++) {
            int idx = tid + t * 256;
            int k  = idx >> 5;
            int n4 = (idx & 31) << 2;
            cp16(Bb + k * NP + n4, Bm + (size_t)(k0 + k) * N + bn + n4);
        }
        cp_commit();
    };

    float acc[2][8][4];
    #pragma unroll
    for (int mt = 0; mt < 2; mt++)
        #pragma unroll
        for (int nt = 0; nt < 8; nt++)
            #pragma unroll
            for (int i = 0; i < 4; i++) acc[mt][nt][i] = 0.f;

    // fragment smem base offsets (element units)
    int aoff = (warp_m + (lane >> 2)) * AP + (lane & 3);
    int boff = (lane & 3) * NP + warp_n + (lane >> 2);

    load_tile(0, 0);

    for (int it = 0; it < kIters; ++it) {
        cp_wait0();
        __syncthreads();
        int cur = it & 1;
        if (it + 1 < kIters) load_tile(it + 1, cur ^ 1);

        const float* Ab = As + cur * ASZ;
        const float* Bb = Bs + cur * BSZ;

        #pragma unroll
        for (int k8 = 0; k8 < 4; ++k8) {
            uint32_t af[2][4], bf[8][2];
            #pragma unroll
            for (int mt = 0; mt < 2; mt++) {
                const float* p = Ab + aoff + mt * 16 * AP + k8 * 8;
                af[mt][0] = __float_as_uint(p[0]);
                af[mt][1] = __float_as_uint(p[8 * AP]);
                af[mt][2] = __float_as_uint(p[4]);
                af[mt][3] = __float_as_uint(p[8 * AP + 4]);
            }
            #pragma unroll
            for (int nt = 0; nt < 8; nt++) {
                const float* p = Bb + boff + k8 * 8 * NP + nt * 8;
                bf[nt][0] = __float_as_uint(p[0]);
                bf[nt][1] = __float_as_uint(p[4 * NP]);
            }
            #pragma unroll
            for (int mt = 0; mt < 2; mt++)
                #pragma unroll
                for (int nt = 0; nt < 8; nt++)
                    mma_tf32(acc[mt][nt], af[mt], bf[nt]);
        }
        __syncthreads();
    }

    // ---------------- epilogue ----------------
    #pragma unroll
    for (int mt = 0; mt < 2; mt++) {
        int row0 = bm + warp_m + mt * 16 + (lane >> 2);
        #pragma unroll
        for (int nt = 0; nt < 8; nt++) {
            int col = bn + warp_n + nt * 8 + (lane & 3) * 2;
            float b0 = bias[col], b1 = bias[col + 1];
            #pragma unroll
            for (int half = 0; half < 2; half++) {
                int r = row0 + half * 8;
                float v0 = acc[mt][nt][half * 2 + 0] + b0;
                float v1 = acc[mt][nt][half * 2 + 1] + b1;
                if (epi == EPI_BIAS_RES) {
                    const float* rr = res + (size_t)r * N;
                    v0 += rr[col]; v1 += rr[col + 1];
                } else if (epi == EPI_GELU) {
                    v0 = 0.5f * v0 * (1.0f + erff(v0 * 0.70710678118654752f));
                    v1 = 0.5f * v1 * (1.0f + erff(v1 * 0.70710678118654752f));
                }
                *(float2*)(C + (size_t)r * N + col) = make_float2(v0, v1);
            }
        }
    }
}

// ---------------- windowed attention (unchanged fp32 SIMT) ----------------
#define SW 324   // padded score row width (max keys = 320)

__global__ void __launch_bounds__(256)
attn_kernel(const float* __restrict__ qkv, float* __restrict__ attn)
{
    int qt = blockIdx.x;
    int h  = blockIdx.y;
    int b  = blockIdx.z;
    int q0 = qt * 64;
    int jstart = max(0, q0 - HALF_WIN);
    int jend1  = min(SEQ_L, q0 + 64 + HALF_WIN);
    int nk = jend1 - jstart;
    int ntiles = nk >> 6;

    extern __shared__ float sm[];
    float* Qs = sm;                  // [64][65]
    float* Ks = Qs + 64 * 65;        // [64][65]
    float* Vs = Ks + 64 * 65;        // [64][65]
    float* Ss = Vs + 64 * 65;        // [64][SW]

    int tid = threadIdx.x;
    int tx = tid & 15, ty = tid >> 4;

    {
        const float* qbase = qkv + ((size_t)(b * SEQ_L + q0)) * 3072 + h * 64;
        for (int idx = tid; idx < 64 * 64; idx += 256) {
            int r = idx >> 6, c = idx & 63;
            Qs[r * 65 + c] = qbase[(size_t)r * 3072 + c] * 0.125f;
        }
    }

    for (int t = 0; t < ntiles; ++t) {
        int jb = jstart + t * 64;
        const float* kbase = qkv + ((size_t)(b * SEQ_L + jb)) * 3072 + 1024 + h * 64;
        __syncthreads();
        for (int idx = tid; idx < 64 * 64; idx += 256) {
            int r = idx >> 6, c = idx & 63;
            Ks[r * 65 + c] = kbase[(size_t)r * 3072 + c];
        }
        __syncthreads();

        float acc[4][4];
        #pragma unroll
        for (int i = 0; i < 4; i++)
            #pragma unroll
            for (int j = 0; j < 4; j++) acc[i][j] = 0.f;

        #pragma unroll 4
        for (int d = 0; d < 64; ++d) {
            float qv[4], kv[4];
            #pragma unroll
            for (int i = 0; i < 4; i++) qv[i] = Qs[(ty * 4 + i) * 65 + d];
            #pragma unroll
            for (int j = 0; j < 4; j++) kv[j] = Ks[(tx * 4 + j) * 65 + d];
            #pragma unroll
            for (int i = 0; i < 4; i++)
                #pragma unroll
                for (int j = 0; j < 4; j++)
                    acc[i][j] = fmaf(qv[i], kv[j], acc[i][j]);
        }

        #pragma unroll
        for (int i = 0; i < 4; i++) {
            int qi = q0 + ty * 4 + i;
            #pragma unroll
            for (int j = 0; j < 4; j++) {
                int jg = jb + tx * 4 + j;
                int dd = jg - qi;
                float s = (dd >= -HALF_WIN && dd <= HALF_WIN) ? acc[i][j] : -INFINITY;
                Ss[(ty * 4 + i) * SW + t * 64 + tx * 4 + j] = s;
            }
        }
    }
    __syncthreads();

    {
        int warp = tid >> 5, lane = tid & 31;
        for (int r = warp; r < 64; r += 8) {
            float* row = Ss + r * SW;
            float m = -INFINITY;
            for (int c = lane; c < nk; c += 32) m = fmaxf(m, row[c]);
            m = warp_max(m);
            float ssum = 0.f;
            for (int c = lane; c < nk; c += 32) {
                float e = expf(row[c] - m);
                row[c] = e;
                ssum += e;
            }
            ssum = warp_sum(ssum);
            float inv = 1.f / ssum;
            for (int c = lane; c < nk; c += 32) row[c] *= inv;
        }
    }

    float oacc[4][4];
    #pragma unroll
    for (int i = 0; i < 4; i++)
        #pragma unroll
        for (int j = 0; j < 4; j++) oacc[i][j] = 0.f;

    for (int t = 0; t < ntiles; ++t) {
        int jb = jstart + t * 64;
        const float* vbase = qkv + ((size_t)(b * SEQ_L + jb)) * 3072 + 2048 + h * 64;
        __syncthreads();
        for (int idx = tid; idx < 64 * 64; idx += 256) {
            int r = idx >> 6, c = idx & 63;
            Vs[r * 65 + c] = vbase[(size_t)r * 3072 + c];
        }
        __syncthreads();

        #pragma unroll 4
        for (int jj = 0; jj < 64; ++jj) {
            float pv[4], vv[4];
            #pragma unroll
            for (int i = 0; i < 4; i++) pv[i] = Ss[(ty * 4 + i) * SW + t * 64 + jj];
            #pragma unroll
            for (int j = 0; j < 4; j++) vv[j] = Vs[jj * 65 + tx * 4 + j];
            #pragma unroll
            for (int i = 0; i < 4; i++)
                #pragma unroll
                for (int j = 0; j < 4; j++)
                    oacc[i][j] = fmaf(pv[i], vv[j], oacc[i][j]);
        }
    }

    #pragma unroll
    for (int i = 0; i < 4; i++) {
        size_t rbase = ((size_t)(b * SEQ_L + q0 + ty * 4 + i)) * D_MODEL + h * 64 + tx * 4;
        #pragma unroll
        for (int j = 0; j < 4; j++)
            attn[rbase + j] = oacc[i][j];
    }
}

// ---------------- launch ----------------
extern "C" void kernel_launch(void* const* d_in, const int* in_sizes, int n_in,
                              void* d_out, int out_size)
{
    const float* x      = (const float*)d_in[0];
    const float* qkv_w  = (const float*)d_in[1];
    const float* qkv_b  = (const float*)d_in[2];
    const float* out_w  = (const float*)d_in[3];
    const float* out_b  = (const float*)d_in[4];
    const float* ln1_g  = (const float*)d_in[5];
    const float* ln1_b  = (const float*)d_in[6];
    const float* ln2_g  = (const float*)d_in[7];
    const float* ln2_b  = (const float*)d_in[8];
    const float* ffn_w1 = (const float*)d_in[9];
    const float* ffn_b1 = (const float*)d_in[10];
    const float* ffn_w2 = (const float*)d_in[11];
    const float* ffn_b2 = (const float*)d_in[12];
    float* out = (float*)d_out;

    float *h, *qkv, *att, *x1, *h2, *ff;
    cudaGetSymbolAddress((void**)&h,   g_h);
    cudaGetSymbolAddress((void**)&qkv, g_qkv);
    cudaGetSymbolAddress((void**)&att, g_att);
    cudaGetSymbolAddress((void**)&x1,  g_x1);
    cudaGetSymbolAddress((void**)&h2,  g_h2);
    cudaGetSymbolAddress((void**)&ff,  g_ff);

    int attn_smem = (3 * 64 * 65 + 64 * SW) * (int)sizeof(float);
    cudaFuncSetAttribute(attn_kernel, cudaFuncAttributeMaxDynamicSharedMemorySize, attn_smem);
    cudaFuncSetAttribute(gemm_tc_kernel, cudaFuncAttributeMaxDynamicSharedMemorySize, (int)GEMM_SMEM);

    // 1) LN1
    ln_kernel<<<NTOK, 256>>>(x, ln1_g, ln1_b, h);
    // 2) QKV projection (tf32 TC)
    gemm_tc_kernel<<<dim3(3 * D_MODEL / 128, NTOK / 128), 256, GEMM_SMEM>>>(
        h, qkv_w, qkv_b, nullptr, qkv, NTOK, 3 * D_MODEL, D_MODEL, EPI_BIAS);
    // 3) windowed attention
    attn_kernel<<<dim3(SEQ_L / 64, N_HEADS, BATCH), 256, attn_smem>>>(qkv, att);
    // 4) output projection + residual (tf32 TC)
    gemm_tc_kernel<<<dim3(D_MODEL / 128, NTOK / 128), 256, GEMM_SMEM>>>(
        att, out_w, out_b, x, x1, NTOK, D_MODEL, D_MODEL, EPI_BIAS_RES);
    // 5) LN2
    ln_kernel<<<NTOK, 256>>>(x1, ln2_g, ln2_b, h2);
    // 6) FFN1 + GELU (tf32 TC)
    gemm_tc_kernel<<<dim3(2 * D_MODEL / 128, NTOK / 128), 256, GEMM_SMEM>>>(
        h2, ffn_w1, ffn_b1, nullptr, ff, NTOK, 2 * D_MODEL, D_MODEL, EPI_GELU);
    // 7) FFN2 + residual -> out (tf32 TC)
    gemm_tc_kernel<<<dim3(D_MODEL / 128, NTOK / 128), 256, GEMM_SMEM>>>(
        ff, ffn_w2, ffn_b2, x1, out, NTOK, D_MODEL, 2 * D_MODEL, EPI_BIAS_RES);
}

// round 4
// speedup vs baseline: 3.0912x; 1.1336x over previous
#include <cuda_runtime.h>
#include <math.h>
#include <stdint.h>

#define D_MODEL   1024
#define N_HEADS   16
#define HEAD_DIM  64
#define SEQ_L     2048
#define BATCH     2
#define NTOK      (BATCH * SEQ_L)      // 4096
#define HALF_WIN  128                  // WINDOW//2
#define LN_EPS    1e-5f

// ---------------- scratch (no allocation allowed) ----------------
__device__ float g_h  [NTOK * D_MODEL];      // LN1 output
__device__ float g_qkv[NTOK * 3 * D_MODEL];  // qkv projection
__device__ float g_att[NTOK * D_MODEL];      // attention output (token-major)
__device__ float g_x1 [NTOK * D_MODEL];      // x + attn_out
__device__ float g_h2 [NTOK * D_MODEL];      // LN2 output
__device__ float g_ff [NTOK * 2 * D_MODEL];  // gelu(ffn1)

// ---------------- helpers ----------------
__inline__ __device__ float warp_sum(float v) {
    #pragma unroll
    for (int o = 16; o > 0; o >>= 1) v += __shfl_xor_sync(0xffffffffu, v, o);
    return v;
}
__inline__ __device__ float warp_max(float v) {
    #pragma unroll
    for (int o = 16; o > 0; o >>= 1) v = fmaxf(v, __shfl_xor_sync(0xffffffffu, v, o));
    return v;
}

__device__ __forceinline__ void cp16(void* smem_dst, const void* gmem_src) {
    uint32_t s = (uint32_t)__cvta_generic_to_shared(smem_dst);
    asm volatile("cp.async.cg.shared.global [%0], [%1], 16;\n" :: "r"(s), "l"(gmem_src));
}
__device__ __forceinline__ void cp_commit() { asm volatile("cp.async.commit_group;\n"); }
__device__ __forceinline__ void cp_wait1()  { asm volatile("cp.async.wait_group 1;\n"); }

__device__ __forceinline__ void mma_tf32(float* c, const uint32_t* a, const uint32_t* b) {
    asm volatile(
        "mma.sync.aligned.m16n8k8.row.col.f32.tf32.tf32.f32 "
        "{%0,%1,%2,%3}, {%4,%5,%6,%7}, {%8,%9}, {%0,%1,%2,%3};\n"
        : "+f"(c[0]), "+f"(c[1]), "+f"(c[2]), "+f"(c[3])
        : "r"(a[0]), "r"(a[1]), "r"(a[2]), "r"(a[3]), "r"(b[0]), "r"(b[1]));
}

// ---------------- LayerNorm: one block per token ----------------
__global__ void __launch_bounds__(256)
ln_kernel(const float* __restrict__ x, const float* __restrict__ g,
          const float* __restrict__ b, float* __restrict__ out)
{
    int row = blockIdx.x;
    const float* xr = x + (size_t)row * D_MODEL;
    float*       orow = out + (size_t)row * D_MODEL;
    int tid = threadIdx.x;

    float v[4];
    float s = 0.f, ss = 0.f;
    #pragma unroll
    for (int i = 0; i < 4; i++) {
        v[i] = xr[tid + i * 256];
        s  += v[i];
        ss += v[i] * v[i];
    }
    __shared__ float shs[8], shss[8], fin[2];
    int lane = tid & 31, warp = tid >> 5;
    s = warp_sum(s); ss = warp_sum(ss);
    if (lane == 0) { shs[warp] = s; shss[warp] = ss; }
    __syncthreads();
    if (tid == 0) {
        float a = 0.f, c = 0.f;
        #pragma unroll
        for (int i = 0; i < 8; i++) { a += shs[i]; c += shss[i]; }
        fin[0] = a; fin[1] = c;
    }
    __syncthreads();
    float mu  = fin[0] * (1.f / D_MODEL);
    float var = fin[1] * (1.f / D_MODEL) - mu * mu;
    float inv = rsqrtf(var + LN_EPS);
    #pragma unroll
    for (int i = 0; i < 4; i++) {
        int c = tid + i * 256;
        orow[c] = (v[i] - mu) * inv * g[c] + b[c];
    }
}

// =================================================================
//  tf32 tensor-core GEMM: C[M,N] = A[M,K] @ B[K,N] + bias (+res / gelu)
//  128x128 block tile, BK=32, 8 warps (4x2), warp tile 32x64,
//  mma.sync.m16n8k8.tf32, 3-stage cp.async pipeline, 1 barrier/iter.
// =================================================================
#define EPI_BIAS     0
#define EPI_BIAS_RES 1
#define EPI_GELU     2

#define AP 36    // A smem row pitch (floats)
#define NP 136   // B smem row pitch (floats)
#define ASZ (128 * AP)   // 4608 floats per A buffer
#define BSZ (32  * NP)   // 4352 floats per B buffer
#define STAGES 3
#define GEMM_SMEM ((STAGES * (ASZ + BSZ)) * sizeof(float))   // 107520 B

__global__ void __launch_bounds__(256)
gemm_tc_kernel(const float* __restrict__ A, const float* __restrict__ Bm,
               const float* __restrict__ bias, const float* __restrict__ res,
               float* __restrict__ C, int M, int N, int K, int epi)
{
    extern __shared__ float smem[];
    float* As = smem;                    // [STAGES][128][AP]
    float* Bs = smem + STAGES * ASZ;     // [STAGES][32][NP]

    int tid  = threadIdx.x;
    int lane = tid & 31;
    int warp = tid >> 5;
    int warp_m = (warp & 3) * 32;   // 4 warps down M
    int warp_n = (warp >> 2) * 64;  // 2 warps across N
    int bm = blockIdx.y * 128;
    int bn = blockIdx.x * 128;

    const int kIters = K >> 5;

    auto load_tile = [&](int it, int buf) {
        int k0 = it << 5;
        float* Ab = As + buf * ASZ;
        float* Bb = Bs + buf * BSZ;
        #pragma unroll
        for (int t = 0; t < 4; t++) {
            int idx = tid + t * 256;
            int m  = idx >> 3;
            int k4 = (idx & 7) << 2;
            cp16(Ab + m * AP + k4, A + (size_t)(bm + m) * K + k0 + k4);
        }
        #pragma unroll
        for (int t = 0; t < 4; t++) {
            int idx = tid + t * 256;
            int k  = idx >> 5;
            int n4 = (idx & 31) << 2;
            cp16(Bb + k * NP + n4, Bm + (size_t)(k0 + k) * N + bn + n4);
        }
    };

    float acc[2][8][4];
    #pragma unroll
    for (int mt = 0; mt < 2; mt++)
        #pragma unroll
        for (int nt = 0; nt < 8; nt++)
            #pragma unroll
            for (int i = 0; i < 4; i++) acc[mt][nt][i] = 0.f;

    int aoff = (warp_m + (lane >> 2)) * AP + (lane & 3);
    int boff = (lane & 3) * NP + warp_n + (lane >> 2);

    load_tile(0, 0); cp_commit();
    load_tile(1, 1); cp_commit();

    int cur = 0;
    for (int it = 0; it < kIters; ++it) {
        cp_wait1();
        __syncthreads();
        if (it + 2 < kIters) {
            int buf = cur + 2; if (buf >= STAGES) buf -= STAGES;
            load_tile(it + 2, buf);
        }
        cp_commit();   // always: keeps group accounting uniform

        const float* Ab = As + cur * ASZ;
        const float* Bb = Bs + cur * BSZ;

        #pragma unroll
        for (int k8 = 0; k8 < 4; ++k8) {
            uint32_t af[2][4], bf[8][2];
            #pragma unroll
            for (int mt = 0; mt < 2; mt++) {
                const float* p = Ab + aoff + mt * 16 * AP + k8 * 8;
                af[mt][0] = __float_as_uint(p[0]);
                af[mt][1] = __float_as_uint(p[8 * AP]);
                af[mt][2] = __float_as_uint(p[4]);
                af[mt][3] = __float_as_uint(p[8 * AP + 4]);
            }
            #pragma unroll
            for (int nt = 0; nt < 8; nt++) {
                const float* p = Bb + boff + k8 * 8 * NP + nt * 8;
                bf[nt][0] = __float_as_uint(p[0]);
                bf[nt][1] = __float_as_uint(p[4 * NP]);
            }
            #pragma unroll
            for (int mt = 0; mt < 2; mt++)
                #pragma unroll
                for (int nt = 0; nt < 8; nt++)
                    mma_tf32(acc[mt][nt], af[mt], bf[nt]);
        }
        cur = cur + 1; if (cur >= STAGES) cur -= STAGES;
    }

    // ---------------- epilogue ----------------
    #pragma unroll
    for (int mt = 0; mt < 2; mt++) {
        int row0 = bm + warp_m + mt * 16 + (lane >> 2);
        #pragma unroll
        for (int nt = 0; nt < 8; nt++) {
            int col = bn + warp_n + nt * 8 + (lane & 3) * 2;
            float b0 = bias[col], b1 = bias[col + 1];
            #pragma unroll
            for (int half = 0; half < 2; half++) {
                int r = row0 + half * 8;
                float v0 = acc[mt][nt][half * 2 + 0] + b0;
                float v1 = acc[mt][nt][half * 2 + 1] + b1;
                if (epi == EPI_BIAS_RES) {
                    const float* rr = res + (size_t)r * N;
                    v0 += rr[col]; v1 += rr[col + 1];
                } else if (epi == EPI_GELU) {
                    v0 = 0.5f * v0 * (1.0f + erff(v0 * 0.70710678118654752f));
                    v1 = 0.5f * v1 * (1.0f + erff(v1 * 0.70710678118654752f));
                }
                *(float2*)(C + (size_t)r * N + col) = make_float2(v0, v1);
            }
        }
    }
}

// =================================================================
//  windowed attention on tensor cores (tf32 mma)
//  grid (L/64, H, B), 256 threads. Per block: 64 queries of one head.
//  Fixed 5 key-tiles of 64 covering [q0-128, q0+192); invalid cols masked.
//  Warp (mw, nw): mw = warp&3 -> 16 rows, nw = warp>>2 -> 32 cols.
// =================================================================
#define SW 324   // Ss row pitch (floats); 320 scores per row

__global__ void __launch_bounds__(256)
attn_tc_kernel(const float* __restrict__ qkv, float* __restrict__ attn)
{
    const int qt = blockIdx.x;
    const int h  = blockIdx.y;
    const int b  = blockIdx.z;
    const int q0 = qt * 64;
    const int j0 = q0 - HALF_WIN;

    extern __shared__ float sm[];
    float* Qs = sm;                  // [64][68]
    float* Ks = Qs + 64 * 68;        // [64][68]
    float* Vt = Ks + 64 * 68;        // [64 d][68 j]  (transposed V)
    float* Ss = Vt + 64 * 68;        // [64][SW]

    const int tid = threadIdx.x;
    const int lane = tid & 31, warp = tid >> 5;
    const int mw = warp & 3, nw = warp >> 2;
    const int lr = lane >> 2, lc = lane & 3;

    const size_t base = (size_t)(b * SEQ_L) * 3072 + (size_t)h * 64;

    // ---- load Q (pre-scaled by 1/sqrt(hd)) ----
    for (int idx = tid; idx < 64 * 64; idx += 256) {
        int r = idx >> 6, c = idx & 63;
        Qs[r * 68 + c] = qkv[base + (size_t)(q0 + r) * 3072 + c] * 0.125f;
    }

    // ---- S = Q @ K^T (per 64-key tile), masked into Ss ----
    for (int t = 0; t < 5; ++t) {
        int jb = j0 + t * 64;
        __syncthreads();
        for (int idx = tid; idx < 64 * 64; idx += 256) {
            int r = idx >> 6, c = idx & 63;
            int j = jb + r; j = min(max(j, 0), SEQ_L - 1);   // clamp; masked later
            Ks[r * 68 + c] = qkv[base + (size_t)j * 3072 + 1024 + c];
        }
        __syncthreads();

        float acc[4][4];
        #pragma unroll
        for (int nt = 0; nt < 4; nt++)
            #pragma unroll
            for (int e = 0; e < 4; e++) acc[nt][e] = 0.f;

        #pragma unroll
        for (int k8 = 0; k8 < 8; ++k8) {
            const float* ap = Qs + (mw * 16 + lr) * 68 + k8 * 8 + lc;
            uint32_t af[4];
            af[0] = __float_as_uint(ap[0]);
            af[1] = __float_as_uint(ap[8 * 68]);
            af[2] = __float_as_uint(ap[4]);
            af[3] = __float_as_uint(ap[8 * 68 + 4]);
            #pragma unroll
            for (int nt = 0; nt < 4; ++nt) {
                const float* bp = Ks + (nw * 32 + nt * 8 + lr) * 68 + k8 * 8 + lc;
                uint32_t bf[2];
                bf[0] = __float_as_uint(bp[0]);
                bf[1] = __float_as_uint(bp[4]);
                mma_tf32(acc[nt], af, bf);
            }
        }

        #pragma unroll
        for (int nt = 0; nt < 4; ++nt) {
            #pragma unroll
            for (int e = 0; e < 4; ++e) {
                int rl = mw * 16 + lr + (e >> 1) * 8;
                int cl = t * 64 + nw * 32 + nt * 8 + 2 * lc + (e & 1);
                int j  = j0 + cl;
                int dd = cl - rl - HALF_WIN;                 // j - i
                bool ok = (j >= 0) && (j < SEQ_L) && (dd >= -HALF_WIN) && (dd <= HALF_WIN);
                Ss[rl * SW + cl] = ok ? acc[nt][e] : -INFINITY;
            }
        }
    }
    __syncthreads();

    // ---- softmax over 320 entries per row (8 warps x 8 rows) ----
    for (int r = warp; r < 64; r += 8) {
        float* row = Ss + r * SW;
        float m = -INFINITY;
        #pragma unroll
        for (int k = 0; k < 10; ++k) m = fmaxf(m, row[lane + k * 32]);
        m = warp_max(m);
        float s = 0.f;
        #pragma unroll
        for (int k = 0; k < 10; ++k) {
            float e = __expf(row[lane + k * 32] - m);
            row[lane + k * 32] = e;
            s += e;
        }
        s = warp_sum(s);
        float inv = 1.f / s;
        #pragma unroll
        for (int k = 0; k < 10; ++k) row[lane + k * 32] *= inv;
    }

    // ---- O = P @ V ----
    float oacc[4][4];
    #pragma unroll
    for (int nt = 0; nt < 4; nt++)
        #pragma unroll
        for (int e = 0; e < 4; e++) oacc[nt][e] = 0.f;

    for (int t = 0; t < 5; ++t) {
        int jb = j0 + t * 64;
        __syncthreads();
        for (int idx = tid; idx < 64 * 64; idx += 256) {
            int r = idx >> 6, c = idx & 63;            // r = local j, c = d
            int j = jb + r; j = min(max(j, 0), SEQ_L - 1);
            Vt[c * 68 + r] = qkv[base + (size_t)j * 3072 + 2048 + c];
        }
        __syncthreads();

        #pragma unroll
        for (int k8 = 0; k8 < 8; ++k8) {
            const float* ap = Ss + (mw * 16 + lr) * SW + t * 64 + k8 * 8 + lc;
            uint32_t af[4];
            af[0] = __float_as_uint(ap[0]);
            af[1] = __float_as_uint(ap[8 * SW]);
            af[2] = __float_as_uint(ap[4]);
            af[3] = __float_as_uint(ap[8 * SW + 4]);
            #pragma unroll
            for (int nt = 0; nt < 4; ++nt) {
                const float* bp = Vt + (nw * 32 + nt * 8 + lr) * 68 + k8 * 8 + lc;
                uint32_t bf[2];
                bf[0] = __float_as_uint(bp[0]);
                bf[1] = __float_as_uint(bp[4]);
                mma_tf32(oacc[nt], af, bf);
            }
        }
    }

    // ---- write O (token-major, head slice) ----
    #pragma unroll
    for (int nt = 0; nt < 4; ++nt) {
        int col = h * 64 + nw * 32 + nt * 8 + 2 * lc;
        #pragma unroll
        for (int half = 0; half < 2; ++half) {
            int r = q0 + mw * 16 + lr + half * 8;
            *(float2*)(attn + (size_t)(b * SEQ_L + r) * D_MODEL + col)
                = make_float2(oacc[nt][half * 2], oacc[nt][half * 2 + 1]);
        }
    }
}

#define ATTN_SMEM ((3 * 64 * 68 + 64 * SW) * sizeof(float))   // 135168 B

// ---------------- launch ----------------
extern "C" void kernel_launch(void* const* d_in, const int* in_sizes, int n_in,
                              void* d_out, int out_size)
{
    const float* x      = (const float*)d_in[0];
    const float* qkv_w  = (const float*)d_in[1];
    const float* qkv_b  = (const float*)d_in[2];
    const float* out_w  = (const float*)d_in[3];
    const float* out_b  = (const float*)d_in[4];
    const float* ln1_g  = (const float*)d_in[5];
    const float* ln1_b  = (const float*)d_in[6];
    const float* ln2_g  = (const float*)d_in[7];
    const float* ln2_b  = (const float*)d_in[8];
    const float* ffn_w1 = (const float*)d_in[9];
    const float* ffn_b1 = (const float*)d_in[10];
    const float* ffn_w2 = (const float*)d_in[11];
    const float* ffn_b2 = (const float*)d_in[12];
    float* out = (float*)d_out;

    float *h, *qkv, *att, *x1, *h2, *ff;
    cudaGetSymbolAddress((void**)&h,   g_h);
    cudaGetSymbolAddress((void**)&qkv, g_qkv);
    cudaGetSymbolAddress((void**)&att, g_att);
    cudaGetSymbolAddress((void**)&x1,  g_x1);
    cudaGetSymbolAddress((void**)&h2,  g_h2);
    cudaGetSymbolAddress((void**)&ff,  g_ff);

    cudaFuncSetAttribute(attn_tc_kernel, cudaFuncAttributeMaxDynamicSharedMemorySize, (int)ATTN_SMEM);
    cudaFuncSetAttribute(gemm_tc_kernel, cudaFuncAttributeMaxDynamicSharedMemorySize, (int)GEMM_SMEM);

    // 1) LN1
    ln_kernel<<<NTOK, 256>>>(x, ln1_g, ln1_b, h);
    // 2) QKV projection (tf32 TC)
    gemm_tc_kernel<<<dim3(3 * D_MODEL / 128, NTOK / 128), 256, GEMM_SMEM>>>(
        h, qkv_w, qkv_b, nullptr, qkv, NTOK, 3 * D_MODEL, D_MODEL, EPI_BIAS);
    // 3) windowed attention (tf32 TC)
    attn_tc_kernel<<<dim3(SEQ_L / 64, N_HEADS, BATCH), 256, ATTN_SMEM>>>(qkv, att);
    // 4) output projection + residual (tf32 TC)
    gemm_tc_kernel<<<dim3(D_MODEL / 128, NTOK / 128), 256, GEMM_SMEM>>>(
        att, out_w, out_b, x, x1, NTOK, D_MODEL, D_MODEL, EPI_BIAS_RES);
    // 5) LN2
    ln_kernel<<<NTOK, 256>>>(x1, ln2_g, ln2_b, h2);
    // 6) FFN1 + GELU (tf32 TC)
    gemm_tc_kernel<<<dim3(2 * D_MODEL / 128, NTOK / 128), 256, GEMM_SMEM>>>(
        h2, ffn_w1, ffn_b1, nullptr, ff, NTOK, 2 * D_MODEL, D_MODEL, EPI_GELU);
    // 7) FFN2 + residual -> out (tf32 TC)
    gemm_tc_kernel<<<dim3(D_MODEL / 128, NTOK / 128), 256, GEMM_SMEM>>>(
        ff, ffn_w2, ffn_b2, x1, out, NTOK, D_MODEL, 2 * D_MODEL, EPI_BIAS_RES);
}

// round 5
// speedup vs baseline: 4.5889x; 1.4845x over previous
#include <cuda_runtime.h>
#include <cuda_fp16.h>
#include <math.h>
#include <stdint.h>

#define D_MODEL   1024
#define N_HEADS   16
#define HEAD_DIM  64
#define SEQ_L     2048
#define BATCH     2
#define NTOK      (BATCH * SEQ_L)      // 4096
#define HALF_WIN  128                  // WINDOW//2
#define LN_EPS    1e-5f

// ---------------- scratch (no allocation allowed) ----------------
__device__ float  g_qkv[NTOK * 3 * D_MODEL];   // qkv projection (fp32, for attention)
__device__ float  g_x1 [NTOK * D_MODEL];       // x + attn_out (fp32)
__device__ __half g_h16 [NTOK * D_MODEL];      // LN1 out, then reused for LN2 out
__device__ __half g_att16[NTOK * D_MODEL];     // attention output (fp16)
__device__ __half g_ff16 [NTOK * 2 * D_MODEL]; // gelu(ffn1) (fp16)
__device__ __half g_wq16 [D_MODEL * 3 * D_MODEL];
__device__ __half g_wo16 [D_MODEL * D_MODEL];
__device__ __half g_w116 [D_MODEL * 2 * D_MODEL];
__device__ __half g_w216 [2 * D_MODEL * D_MODEL];

// ---------------- helpers ----------------
__inline__ __device__ float warp_sum(float v) {
    #pragma unroll
    for (int o = 16; o > 0; o >>= 1) v += __shfl_xor_sync(0xffffffffu, v, o);
    return v;
}
__inline__ __device__ float warp_max(float v) {
    #pragma unroll
    for (int o = 16; o > 0; o >>= 1) v = fmaxf(v, __shfl_xor_sync(0xffffffffu, v, o));
    return v;
}

__device__ __forceinline__ void cp16(void* smem_dst, const void* gmem_src) {
    uint32_t s = (uint32_t)__cvta_generic_to_shared(smem_dst);
    asm volatile("cp.async.cg.shared.global [%0], [%1], 16;\n" :: "r"(s), "l"(gmem_src));
}
__device__ __forceinline__ void cp_commit() { asm volatile("cp.async.commit_group;\n"); }
__device__ __forceinline__ void cp_wait1()  { asm volatile("cp.async.wait_group 1;\n"); }

__device__ __forceinline__ void mma_tf32(float* c, const uint32_t* a, const uint32_t* b) {
    asm volatile(
        "mma.sync.aligned.m16n8k8.row.col.f32.tf32.tf32.f32 "
        "{%0,%1,%2,%3}, {%4,%5,%6,%7}, {%8,%9}, {%0,%1,%2,%3};\n"
        : "+f"(c[0]), "+f"(c[1]), "+f"(c[2]), "+f"(c[3])
        : "r"(a[0]), "r"(a[1]), "r"(a[2]), "r"(a[3]), "r"(b[0]), "r"(b[1]));
}
__device__ __forceinline__ void mma_f16(float* c, const uint32_t* a, const uint32_t* b) {
    asm volatile(
        "mma.sync.aligned.m16n8k16.row.col.f32.f16.f16.f32 "
        "{%0,%1,%2,%3}, {%4,%5,%6,%7}, {%8,%9}, {%0,%1,%2,%3};\n"
        : "+f"(c[0]), "+f"(c[1]), "+f"(c[2]), "+f"(c[3])
        : "r"(a[0]), "r"(a[1]), "r"(a[2]), "r"(a[3]), "r"(b[0]), "r"(b[1]));
}
__device__ __forceinline__ void ldmx4(uint32_t& r0, uint32_t& r1, uint32_t& r2, uint32_t& r3, uint32_t addr) {
    asm volatile("ldmatrix.sync.aligned.m8n8.x4.shared.b16 {%0,%1,%2,%3}, [%4];\n"
                 : "=r"(r0), "=r"(r1), "=r"(r2), "=r"(r3) : "r"(addr));
}
__device__ __forceinline__ void ldmx4t(uint32_t& r0, uint32_t& r1, uint32_t& r2, uint32_t& r3, uint32_t addr) {
    asm volatile("ldmatrix.sync.aligned.m8n8.x4.trans.shared.b16 {%0,%1,%2,%3}, [%4];\n"
                 : "=r"(r0), "=r"(r1), "=r"(r2), "=r"(r3) : "r"(addr));
}

// ---------------- fp32 -> fp16 conversion (weights) ----------------
__global__ void __launch_bounds__(256)
f2h_kernel(const float4* __restrict__ in, __half2* __restrict__ out, int n4)
{
    int i = blockIdx.x * 256 + threadIdx.x;
    if (i < n4) {
        float4 v = in[i];
        out[2 * i]     = __floats2half2_rn(v.x, v.y);
        out[2 * i + 1] = __floats2half2_rn(v.z, v.w);
    }
}

// ---------------- LayerNorm: one block per token, fp16 output ----------------
__global__ void __launch_bounds__(256)
ln_kernel(const float* __restrict__ x, const float* __restrict__ g,
          const float* __restrict__ b, __half* __restrict__ out)
{
    int row = blockIdx.x;
    const float* xr = x + (size_t)row * D_MODEL;
    __half*      orow = out + (size_t)row * D_MODEL;
    int tid = threadIdx.x;

    float v[4];
    float s = 0.f, ss = 0.f;
    #pragma unroll
    for (int i = 0; i < 4; i++) {
        v[i] = xr[tid + i * 256];
        s  += v[i];
        ss += v[i] * v[i];
    }
    __shared__ float shs[8], shss[8], fin[2];
    int lane = tid & 31, warp = tid >> 5;
    s = warp_sum(s); ss = warp_sum(ss);
    if (lane == 0) { shs[warp] = s; shss[warp] = ss; }
    __syncthreads();
    if (tid == 0) {
        float a = 0.f, c = 0.f;
        #pragma unroll
        for (int i = 0; i < 8; i++) { a += shs[i]; c += shss[i]; }
        fin[0] = a; fin[1] = c;
    }
    __syncthreads();
    float mu  = fin[0] * (1.f / D_MODEL);
    float var = fin[1] * (1.f / D_MODEL) - mu * mu;
    float inv = rsqrtf(var + LN_EPS);
    #pragma unroll
    for (int i = 0; i < 4; i++) {
        int c = tid + i * 256;
        orow[c] = __float2half_rn((v[i] - mu) * inv * g[c] + b[c]);
    }
}

// =================================================================
//  fp16 tensor-core GEMM: C[M,N] = A[M,K] @ B[K,N] + bias (+res / gelu)
//  128x128 block tile, BK=32, 8 warps (4x2), warp tile 32x64,
//  mma.sync.m16n8k16.f16.f32acc, ldmatrix fragments, 3-stage cp.async.
// =================================================================
#define EPI_BIAS     0
#define EPI_BIAS_RES 1
#define EPI_GELU_H   2

#define AP16 40      // A smem pitch (halves) = 80B -> conflict-free ldmatrix
#define BP16 136     // B smem pitch (halves) = 272B -> conflict-free trans ldmatrix
#define HASZ (128 * AP16)    // 5120 halves per A stage
#define HBSZ (32  * BP16)    // 4352 halves per B stage
#define STAGES 3
#define GEMM_SMEM ((size_t)STAGES * (HASZ + HBSZ) * sizeof(__half))   // 56832 B

__global__ void __launch_bounds__(256)
gemm_h_kernel(const __half* __restrict__ A, const __half* __restrict__ Bm,
              const float* __restrict__ bias, const float* __restrict__ res,
              float* __restrict__ C, __half* __restrict__ Ch,
              int M, int N, int K, int epi)
{
    extern __shared__ __half hsm[];
    __half* As = hsm;
    __half* Bs = hsm + STAGES * HASZ;
    uint32_t smem_u = (uint32_t)__cvta_generic_to_shared(hsm);

    int tid  = threadIdx.x;
    int lane = tid & 31;
    int warp = tid >> 5;
    int warp_m = (warp & 3) * 32;
    int warp_n = (warp >> 2) * 64;
    int bm = blockIdx.y * 128;
    int bn = blockIdx.x * 128;

    const int kIters = K >> 5;

    auto load_tile = [&](int it, int buf) {
        int k0 = it << 5;
        __half* Ab = As + buf * HASZ;
        __half* Bb = Bs + buf * HBSZ;
        #pragma unroll
        for (int t = 0; t < 2; t++) {
            int idx = tid + t * 256;
            int m  = idx >> 2;
            int c8 = (idx & 3) << 3;
            cp16(Ab + m * AP16 + c8, A + (size_t)(bm + m) * K + k0 + c8);
        }
        #pragma unroll
        for (int t = 0; t < 2; t++) {
            int idx = tid + t * 256;
            int k  = idx >> 4;
            int n8 = (idx & 15) << 3;
            cp16(Bb + k * BP16 + n8, Bm + (size_t)(k0 + k) * N + bn + n8);
        }
    };

    float acc[2][8][4];
    #pragma unroll
    for (int mt = 0; mt < 2; mt++)
        #pragma unroll
        for (int nt = 0; nt < 8; nt++)
            #pragma unroll
            for (int i = 0; i < 4; i++) acc[mt][nt][i] = 0.f;

    // ldmatrix lane addressing (byte offsets within a stage)
    // A: row = warp_m + mt*16 + (lane&15); col(halves) = kk*16 + (lane>>4)*8
    int a_row = warp_m + (lane & 15);
    int a_c8  = (lane >> 4) << 3;
    // B: krow = kk*16 + (lane&15); col = warp_n + np*16 + (lane>>4)*8
    int b_k   = lane & 15;
    int b_c8  = (lane >> 4) << 3;

    load_tile(0, 0); cp_commit();
    load_tile(1, 1); cp_commit();

    int cur = 0;
    for (int it = 0; it < kIters; ++it) {
        cp_wait1();
        __syncthreads();
        if (it + 2 < kIters) {
            int buf = cur + 2; if (buf >= STAGES) buf -= STAGES;
            load_tile(it + 2, buf);
        }
        cp_commit();

        uint32_t Abase = smem_u + (uint32_t)(cur * HASZ) * 2;
        uint32_t Bbase = smem_u + (uint32_t)(STAGES * HASZ + cur * HBSZ) * 2;

        #pragma unroll
        for (int kk = 0; kk < 2; ++kk) {
            uint32_t af[2][4], bf[8][2];
            #pragma unroll
            for (int mt = 0; mt < 2; mt++) {
                uint32_t addr = Abase + ((a_row + mt * 16) * AP16 + kk * 16 + a_c8) * 2;
                ldmx4(af[mt][0], af[mt][1], af[mt][2], af[mt][3], addr);
            }
            #pragma unroll
            for (int np = 0; np < 4; np++) {
                uint32_t addr = Bbase + ((kk * 16 + b_k) * BP16 + warp_n + np * 16 + b_c8) * 2;
                ldmx4t(bf[2 * np][0], bf[2 * np][1], bf[2 * np + 1][0], bf[2 * np + 1][1], addr);
            }
            #pragma unroll
            for (int mt = 0; mt < 2; mt++)
                #pragma unroll
                for (int nt = 0; nt < 8; nt++)
                    mma_f16(acc[mt][nt], af[mt], bf[nt]);
        }
        cur = cur + 1; if (cur >= STAGES) cur -= STAGES;
    }

    // ---------------- epilogue ----------------
    #pragma unroll
    for (int mt = 0; mt < 2; mt++) {
        int row0 = bm + warp_m + mt * 16 + (lane >> 2);
        #pragma unroll
        for (int nt = 0; nt < 8; nt++) {
            int col = bn + warp_n + nt * 8 + (lane & 3) * 2;
            float b0 = bias[col], b1 = bias[col + 1];
            #pragma unroll
            for (int half_ = 0; half_ < 2; half_++) {
                int r = row0 + half_ * 8;
                float v0 = acc[mt][nt][half_ * 2 + 0] + b0;
                float v1 = acc[mt][nt][half_ * 2 + 1] + b1;
                if (epi == EPI_BIAS_RES) {
                    const float* rr = res + (size_t)r * N;
                    v0 += rr[col]; v1 += rr[col + 1];
                    *(float2*)(C + (size_t)r * N + col) = make_float2(v0, v1);
                } else if (epi == EPI_GELU_H) {
                    v0 = 0.5f * v0 * (1.0f + erff(v0 * 0.70710678118654752f));
                    v1 = 0.5f * v1 * (1.0f + erff(v1 * 0.70710678118654752f));
                    *(__half2*)(Ch + (size_t)r * N + col) = __floats2half2_rn(v0, v1);
                } else {
                    *(float2*)(C + (size_t)r * N + col) = make_float2(v0, v1);
                }
            }
        }
    }
}

// =================================================================
//  windowed attention on tensor cores (tf32 mma), fp16 output
// =================================================================
#define SW 324   // Ss row pitch (floats); 320 scores per row

__global__ void __launch_bounds__(256)
attn_tc_kernel(const float* __restrict__ qkv, __half* __restrict__ attn)
{
    const int qt = blockIdx.x;
    const int h  = blockIdx.y;
    const int b  = blockIdx.z;
    const int q0 = qt * 64;
    const int j0 = q0 - HALF_WIN;

    extern __shared__ float sm[];
    float* Qs = sm;                  // [64][68]
    float* Ks = Qs + 64 * 68;        // [64][68]
    float* Vt = Ks + 64 * 68;        // [64 d][68 j]
    float* Ss = Vt + 64 * 68;        // [64][SW]

    const int tid = threadIdx.x;
    const int lane = tid & 31, warp = tid >> 5;
    const int mw = warp & 3, nw = warp >> 2;
    const int lr = lane >> 2, lc = lane & 3;

    const size_t base = (size_t)(b * SEQ_L) * 3072 + (size_t)h * 64;

    for (int idx = tid; idx < 64 * 64; idx += 256) {
        int r = idx >> 6, c = idx & 63;
        Qs[r * 68 + c] = qkv[base + (size_t)(q0 + r) * 3072 + c] * 0.125f;
    }

    for (int t = 0; t < 5; ++t) {
        int jb = j0 + t * 64;
        __syncthreads();
        for (int idx = tid; idx < 64 * 64; idx += 256) {
            int r = idx >> 6, c = idx & 63;
            int j = jb + r; j = min(max(j, 0), SEQ_L - 1);
            Ks[r * 68 + c] = qkv[base + (size_t)j * 3072 + 1024 + c];
        }
        __syncthreads();

        float acc[4][4];
        #pragma unroll
        for (int nt = 0; nt < 4; nt++)
            #pragma unroll
            for (int e = 0; e < 4; e++) acc[nt][e] = 0.f;

        #pragma unroll
        for (int k8 = 0; k8 < 8; ++k8) {
            const float* ap = Qs + (mw * 16 + lr) * 68 + k8 * 8 + lc;
            uint32_t af[4];
            af[0] = __float_as_uint(ap[0]);
            af[1] = __float_as_uint(ap[8 * 68]);
            af[2] = __float_as_uint(ap[4]);
            af[3] = __float_as_uint(ap[8 * 68 + 4]);
            #pragma unroll
            for (int nt = 0; nt < 4; ++nt) {
                const float* bp = Ks + (nw * 32 + nt * 8 + lr) * 68 + k8 * 8 + lc;
                uint32_t bf[2];
                bf[0] = __float_as_uint(bp[0]);
                bf[1] = __float_as_uint(bp[4]);
                mma_tf32(acc[nt], af, bf);
            }
        }

        #pragma unroll
        for (int nt = 0; nt < 4; ++nt) {
            #pragma unroll
            for (int e = 0; e < 4; ++e) {
                int rl = mw * 16 + lr + (e >> 1) * 8;
                int cl = t * 64 + nw * 32 + nt * 8 + 2 * lc + (e & 1);
                int j  = j0 + cl;
                int dd = cl - rl - HALF_WIN;
                bool ok = (j >= 0) && (j < SEQ_L) && (dd >= -HALF_WIN) && (dd <= HALF_WIN);
                Ss[rl * SW + cl] = ok ? acc[nt][e] : -INFINITY;
            }
        }
    }
    __syncthreads();

    for (int r = warp; r < 64; r += 8) {
        float* row = Ss + r * SW;
        float m = -INFINITY;
        #pragma unroll
        for (int k = 0; k < 10; ++k) m = fmaxf(m, row[lane + k * 32]);
        m = warp_max(m);
        float s = 0.f;
        #pragma unroll
        for (int k = 0; k < 10; ++k) {
            float e = __expf(row[lane + k * 32] - m);
            row[lane + k * 32] = e;
            s += e;
        }
        s = warp_sum(s);
        float inv = 1.f / s;
        #pragma unroll
        for (int k = 0; k < 10; ++k) row[lane + k * 32] *= inv;
    }

    float oacc[4][4];
    #pragma unroll
    for (int nt = 0; nt < 4; nt++)
        #pragma unroll
        for (int e = 0; e < 4; e++) oacc[nt][e] = 0.f;

    for (int t = 0; t < 5; ++t) {
        int jb = j0 + t * 64;
        __syncthreads();
        for (int idx = tid; idx < 64 * 64; idx += 256) {
            int r = idx >> 6, c = idx & 63;
            int j = jb + r; j = min(max(j, 0), SEQ_L - 1);
            Vt[c * 68 + r] = qkv[base + (size_t)j * 3072 + 2048 + c];
        }
        __syncthreads();

        #pragma unroll
        for (int k8 = 0; k8 < 8; ++k8) {
            const float* ap = Ss + (mw * 16 + lr) * SW + t * 64 + k8 * 8 + lc;
            uint32_t af[4];
            af[0] = __float_as_uint(ap[0]);
            af[1] = __float_as_uint(ap[8 * SW]);
            af[2] = __float_as_uint(ap[4]);
            af[3] = __float_as_uint(ap[8 * SW + 4]);
            #pragma unroll
            for (int nt = 0; nt < 4; ++nt) {
                const float* bp = Vt + (nw * 32 + nt * 8 + lr) * 68 + k8 * 8 + lc;
                uint32_t bf[2];
                bf[0] = __float_as_uint(bp[0]);
                bf[1] = __float_as_uint(bp[4]);
                mma_tf32(oacc[nt], af, bf);
            }
        }
    }

    #pragma unroll
    for (int nt = 0; nt < 4; ++nt) {
        int col = h * 64 + nw * 32 + nt * 8 + 2 * lc;
        #pragma unroll
        for (int half_ = 0; half_ < 2; ++half_) {
            int r = q0 + mw * 16 + lr + half_ * 8;
            *(__half2*)(attn + (size_t)(b * SEQ_L + r) * D_MODEL + col)
                = __floats2half2_rn(oacc[nt][half_ * 2], oacc[nt][half_ * 2 + 1]);
        }
    }
}

#define ATTN_SMEM ((3 * 64 * 68 + 64 * SW) * sizeof(float))   // 135168 B

// ---------------- launch ----------------
extern "C" void kernel_launch(void* const* d_in, const int* in_sizes, int n_in,
                              void* d_out, int out_size)
{
    const float* x      = (const float*)d_in[0];
    const float* qkv_w  = (const float*)d_in[1];
    const float* qkv_b  = (const float*)d_in[2];
    const float* out_w  = (const float*)d_in[3];
    const float* out_b  = (const float*)d_in[4];
    const float* ln1_g  = (const float*)d_in[5];
    const float* ln1_b  = (const float*)d_in[6];
    const float* ln2_g  = (const float*)d_in[7];
    const float* ln2_b  = (const float*)d_in[8];
    const float* ffn_w1 = (const float*)d_in[9];
    const float* ffn_b1 = (const float*)d_in[10];
    const float* ffn_w2 = (const float*)d_in[11];
    const float* ffn_b2 = (const float*)d_in[12];
    float* out = (float*)d_out;

    float *qkv, *x1;
    __half *h16, *att16, *ff16, *wq16, *wo16, *w116, *w216;
    cudaGetSymbolAddress((void**)&qkv,  g_qkv);
    cudaGetSymbolAddress((void**)&x1,   g_x1);
    cudaGetSymbolAddress((void**)&h16,  g_h16);
    cudaGetSymbolAddress((void**)&att16,g_att16);
    cudaGetSymbolAddress((void**)&ff16, g_ff16);
    cudaGetSymbolAddress((void**)&wq16, g_wq16);
    cudaGetSymbolAddress((void**)&wo16, g_wo16);
    cudaGetSymbolAddress((void**)&w116, g_w116);
    cudaGetSymbolAddress((void**)&w216, g_w216);

    cudaFuncSetAttribute(attn_tc_kernel, cudaFuncAttributeMaxDynamicSharedMemorySize, (int)ATTN_SMEM);
    cudaFuncSetAttribute(gemm_h_kernel,  cudaFuncAttributeMaxDynamicSharedMemorySize, (int)GEMM_SMEM);

    // 0) weight conversions fp32->fp16
    {
        int n4;
        n4 = D_MODEL * 3 * D_MODEL / 4;
        f2h_kernel<<<(n4 + 255) / 256, 256>>>((const float4*)qkv_w, (__half2*)wq16, n4);
        n4 = D_MODEL * D_MODEL / 4;
        f2h_kernel<<<(n4 + 255) / 256, 256>>>((const float4*)out_w, (__half2*)wo16, n4);
        n4 = D_MODEL * 2 * D_MODEL / 4;
        f2h_kernel<<<(n4 + 255) / 256, 256>>>((const float4*)ffn_w1, (__half2*)w116, n4);
        n4 = 2 * D_MODEL * D_MODEL / 4;
        f2h_kernel<<<(n4 + 255) / 256, 256>>>((const float4*)ffn_w2, (__half2*)w216, n4);
    }

    // 1) LN1 -> fp16
    ln_kernel<<<NTOK, 256>>>(x, ln1_g, ln1_b, h16);
    // 2) QKV projection (fp16 TC, fp32 out)
    gemm_h_kernel<<<dim3(3 * D_MODEL / 128, NTOK / 128), 256, GEMM_SMEM>>>(
        h16, wq16, qkv_b, nullptr, qkv, nullptr, NTOK, 3 * D_MODEL, D_MODEL, EPI_BIAS);
    // 3) windowed attention (tf32 TC, fp16 out)
    attn_tc_kernel<<<dim3(SEQ_L / 64, N_HEADS, BATCH), 256, ATTN_SMEM>>>(qkv, att16);
    // 4) output projection + residual (fp16 TC, fp32 out)
    gemm_h_kernel<<<dim3(D_MODEL / 128, NTOK / 128), 256, GEMM_SMEM>>>(
        att16, wo16, out_b, x, x1, nullptr, NTOK, D_MODEL, D_MODEL, EPI_BIAS_RES);
    // 5) LN2 -> fp16
    ln_kernel<<<NTOK, 256>>>(x1, ln2_g, ln2_b, h16);
    // 6) FFN1 + GELU (fp16 TC, fp16 out)
    gemm_h_kernel<<<dim3(2 * D_MODEL / 128, NTOK / 128), 256, GEMM_SMEM>>>(
        h16, w116, ffn_b1, nullptr, nullptr, ff16, NTOK, 2 * D_MODEL, D_MODEL, EPI_GELU_H);
    // 7) FFN2 + residual -> out (fp16 TC, fp32 out)
    gemm_h_kernel<<<dim3(D_MODEL / 128, NTOK / 128), 256, GEMM_SMEM>>>(
        ff16, w216, ffn_b2, x1, out, nullptr, NTOK, D_MODEL, 2 * D_MODEL, EPI_BIAS_RES);
}

// round 6
// speedup vs baseline: 4.5892x; 1.0001x over previous
#include <cuda_runtime.h>
#include <cuda_fp16.h>
#include <math.h>
#include <stdint.h>

#define D_MODEL   1024
#define N_HEADS   16
#define HEAD_DIM  64
#define SEQ_L     2048
#define BATCH     2
#define NTOK      (BATCH * SEQ_L)      // 4096
#define HALF_WIN  128                  // WINDOW//2
#define LN_EPS    1e-5f

// ---------------- scratch (no allocation allowed) ----------------
__device__ float  g_qkv[NTOK * 3 * D_MODEL];   // qkv projection (fp32, for attention)
__device__ float  g_x1 [NTOK * D_MODEL];       // x + attn_out (fp32)
__device__ __half g_h16 [NTOK * D_MODEL];      // LN1 out, then reused for LN2 out
__device__ __half g_att16[NTOK * D_MODEL];     // attention output (fp16)
__device__ __half g_ff16 [NTOK * 2 * D_MODEL]; // gelu(ffn1) (fp16)
__device__ __half g_wq16 [D_MODEL * 3 * D_MODEL];
__device__ __half g_wo16 [D_MODEL * D_MODEL];
__device__ __half g_w116 [D_MODEL * 2 * D_MODEL];
__device__ __half g_w216 [2 * D_MODEL * D_MODEL];

// ---------------- helpers ----------------
__inline__ __device__ float warp_sum(float v) {
    #pragma unroll
    for (int o = 16; o > 0; o >>= 1) v += __shfl_xor_sync(0xffffffffu, v, o);
    return v;
}
__inline__ __device__ float warp_max(float v) {
    #pragma unroll
    for (int o = 16; o > 0; o >>= 1) v = fmaxf(v, __shfl_xor_sync(0xffffffffu, v, o));
    return v;
}

__device__ __forceinline__ void cp16(void* smem_dst, const void* gmem_src) {
    uint32_t s = (uint32_t)__cvta_generic_to_shared(smem_dst);
    asm volatile("cp.async.cg.shared.global [%0], [%1], 16;\n" :: "r"(s), "l"(gmem_src));
}
__device__ __forceinline__ void cp_commit() { asm volatile("cp.async.commit_group;\n"); }
__device__ __forceinline__ void cp_wait1()  { asm volatile("cp.async.wait_group 1;\n"); }

__device__ __forceinline__ void mma_tf32(float* c, const uint32_t* a, const uint32_t* b) {
    asm volatile(
        "mma.sync.aligned.m16n8k8.row.col.f32.tf32.tf32.f32 "
        "{%0,%1,%2,%3}, {%4,%5,%6,%7}, {%8,%9}, {%0,%1,%2,%3};\n"
        : "+f"(c[0]), "+f"(c[1]), "+f"(c[2]), "+f"(c[3])
        : "r"(a[0]), "r"(a[1]), "r"(a[2]), "r"(a[3]), "r"(b[0]), "r"(b[1]));
}
__device__ __forceinline__ void mma_f16(float* c, const uint32_t* a, const uint32_t* b) {
    asm volatile(
        "mma.sync.aligned.m16n8k16.row.col.f32.f16.f16.f32 "
        "{%0,%1,%2,%3}, {%4,%5,%6,%7}, {%8,%9}, {%0,%1,%2,%3};\n"
        : "+f"(c[0]), "+f"(c[1]), "+f"(c[2]), "+f"(c[3])
        : "r"(a[0]), "r"(a[1]), "r"(a[2]), "r"(a[3]), "r"(b[0]), "r"(b[1]));
}
__device__ __forceinline__ void ldmx4(uint32_t& r0, uint32_t& r1, uint32_t& r2, uint32_t& r3, uint32_t addr) {
    asm volatile("ldmatrix.sync.aligned.m8n8.x4.shared.b16 {%0,%1,%2,%3}, [%4];\n"
                 : "=r"(r0), "=r"(r1), "=r"(r2), "=r"(r3) : "r"(addr));
}
__device__ __forceinline__ void ldmx4t(uint32_t& r0, uint32_t& r1, uint32_t& r2, uint32_t& r3, uint32_t addr) {
    asm volatile("ldmatrix.sync.aligned.m8n8.x4.trans.shared.b16 {%0,%1,%2,%3}, [%4];\n"
                 : "=r"(r0), "=r"(r1), "=r"(r2), "=r"(r3) : "r"(addr));
}

// ---------------- fp32 -> fp16 conversion (weights) ----------------
__global__ void __launch_bounds__(256)
f2h_kernel(const float4* __restrict__ in, __half2* __restrict__ out, int n4)
{
    int i = blockIdx.x * 256 + threadIdx.x;
    if (i < n4) {
        float4 v = in[i];
        out[2 * i]     = __floats2half2_rn(v.x, v.y);
        out[2 * i + 1] = __floats2half2_rn(v.z, v.w);
    }
}

// ---------------- LayerNorm: one block per token, fp16 output ----------------
__global__ void __launch_bounds__(256)
ln_kernel(const float* __restrict__ x, const float* __restrict__ g,
          const float* __restrict__ b, __half* __restrict__ out)
{
    int row = blockIdx.x;
    const float* xr = x + (size_t)row * D_MODEL;
    __half*      orow = out + (size_t)row * D_MODEL;
    int tid = threadIdx.x;

    float v[4];
    float s = 0.f, ss = 0.f;
    #pragma unroll
    for (int i = 0; i < 4; i++) {
        v[i] = xr[tid + i * 256];
        s  += v[i];
        ss += v[i] * v[i];
    }
    __shared__ float shs[8], shss[8], fin[2];
    int lane = tid & 31, warp = tid >> 5;
    s = warp_sum(s); ss = warp_sum(ss);
    if (lane == 0) { shs[warp] = s; shss[warp] = ss; }
    __syncthreads();
    if (tid == 0) {
        float a = 0.f, c = 0.f;
        #pragma unroll
        for (int i = 0; i < 8; i++) { a += shs[i]; c += shss[i]; }
        fin[0] = a; fin[1] = c;
    }
    __syncthreads();
    float mu  = fin[0] * (1.f / D_MODEL);
    float var = fin[1] * (1.f / D_MODEL) - mu * mu;
    float inv = rsqrtf(var + LN_EPS);
    #pragma unroll
    for (int i = 0; i < 4; i++) {
        int c = tid + i * 256;
        orow[c] = __float2half_rn((v[i] - mu) * inv * g[c] + b[c]);
    }
}

// =================================================================
//  fp16 tensor-core GEMM: C[M,N] = A[M,K] @ B[K,N] + bias (+res / gelu)
//  128x128 block tile, BK=32, 8 warps (4x2), warp tile 32x64,
//  mma.sync.m16n8k16.f16.f32acc, ldmatrix fragments, 3-stage cp.async.
// =================================================================
#define EPI_BIAS     0
#define EPI_BIAS_RES 1
#define EPI_GELU_H   2

#define AP16 40      // A smem pitch (halves) = 80B -> conflict-free ldmatrix
#define BP16 136     // B smem pitch (halves) = 272B -> conflict-free trans ldmatrix
#define HASZ (128 * AP16)    // 5120 halves per A stage
#define HBSZ (32  * BP16)    // 4352 halves per B stage
#define STAGES 3
#define GEMM_SMEM ((size_t)STAGES * (HASZ + HBSZ) * sizeof(__half))   // 56832 B

__global__ void __launch_bounds__(256)
gemm_h_kernel(const __half* __restrict__ A, const __half* __restrict__ Bm,
              const float* __restrict__ bias, const float* __restrict__ res,
              float* __restrict__ C, __half* __restrict__ Ch,
              int M, int N, int K, int epi)
{
    extern __shared__ __half hsm[];
    __half* As = hsm;
    __half* Bs = hsm + STAGES * HASZ;
    uint32_t smem_u = (uint32_t)__cvta_generic_to_shared(hsm);

    int tid  = threadIdx.x;
    int lane = tid & 31;
    int warp = tid >> 5;
    int warp_m = (warp & 3) * 32;
    int warp_n = (warp >> 2) * 64;
    int bm = blockIdx.y * 128;
    int bn = blockIdx.x * 128;

    const int kIters = K >> 5;

    auto load_tile = [&](int it, int buf) {
        int k0 = it << 5;
        __half* Ab = As + buf * HASZ;
        __half* Bb = Bs + buf * HBSZ;
        #pragma unroll
        for (int t = 0; t < 2; t++) {
            int idx = tid + t * 256;
            int m  = idx >> 2;
            int c8 = (idx & 3) << 3;
            cp16(Ab + m * AP16 + c8, A + (size_t)(bm + m) * K + k0 + c8);
        }
        #pragma unroll
        for (int t = 0; t < 2; t++) {
            int idx = tid + t * 256;
            int k  = idx >> 4;
            int n8 = (idx & 15) << 3;
            cp16(Bb + k * BP16 + n8, Bm + (size_t)(k0 + k) * N + bn + n8);
        }
    };

    float acc[2][8][4];
    #pragma unroll
    for (int mt = 0; mt < 2; mt++)
        #pragma unroll
        for (int nt = 0; nt < 8; nt++)
            #pragma unroll
            for (int i = 0; i < 4; i++) acc[mt][nt][i] = 0.f;

    // ldmatrix lane addressing (byte offsets within a stage)
    // A: row = warp_m + mt*16 + (lane&15); col(halves) = kk*16 + (lane>>4)*8
    int a_row = warp_m + (lane & 15);
    int a_c8  = (lane >> 4) << 3;
    // B: krow = kk*16 + (lane&15); col = warp_n + np*16 + (lane>>4)*8
    int b_k   = lane & 15;
    int b_c8  = (lane >> 4) << 3;

    load_tile(0, 0); cp_commit();
    load_tile(1, 1); cp_commit();

    int cur = 0;
    for (int it = 0; it < kIters; ++it) {
        cp_wait1();
        __syncthreads();
        if (it + 2 < kIters) {
            int buf = cur + 2; if (buf >= STAGES) buf -= STAGES;
            load_tile(it + 2, buf);
        }
        cp_commit();

        uint32_t Abase = smem_u + (uint32_t)(cur * HASZ) * 2;
        uint32_t Bbase = smem_u + (uint32_t)(STAGES * HASZ + cur * HBSZ) * 2;

        #pragma unroll
        for (int kk = 0; kk < 2; ++kk) {
            uint32_t af[2][4], bf[8][2];
            #pragma unroll
            for (int mt = 0; mt < 2; mt++) {
                uint32_t addr = Abase + ((a_row + mt * 16) * AP16 + kk * 16 + a_c8) * 2;
                ldmx4(af[mt][0], af[mt][1], af[mt][2], af[mt][3], addr);
            }
            #pragma unroll
            for (int np = 0; np < 4; np++) {
                uint32_t addr = Bbase + ((kk * 16 + b_k) * BP16 + warp_n + np * 16 + b_c8) * 2;
                ldmx4t(bf[2 * np][0], bf[2 * np][1], bf[2 * np + 1][0], bf[2 * np + 1][1], addr);
            }
            #pragma unroll
            for (int mt = 0; mt < 2; mt++)
                #pragma unroll
                for (int nt = 0; nt < 8; nt++)
                    mma_f16(acc[mt][nt], af[mt], bf[nt]);
        }
        cur = cur + 1; if (cur >= STAGES) cur -= STAGES;
    }

    // ---------------- epilogue ----------------
    #pragma unroll
    for (int mt = 0; mt < 2; mt++) {
        int row0 = bm + warp_m + mt * 16 + (lane >> 2);
        #pragma unroll
        for (int nt = 0; nt < 8; nt++) {
            int col = bn + warp_n + nt * 8 + (lane & 3) * 2;
            float b0 = bias[col], b1 = bias[col + 1];
            #pragma unroll
            for (int half_ = 0; half_ < 2; half_++) {
                int r = row0 + half_ * 8;
                float v0 = acc[mt][nt][half_ * 2 + 0] + b0;
                float v1 = acc[mt][nt][half_ * 2 + 1] + b1;
                if (epi == EPI_BIAS_RES) {
                    const float* rr = res + (size_t)r * N;
                    v0 += rr[col]; v1 += rr[col + 1];
                    *(float2*)(C + (size_t)r * N + col) = make_float2(v0, v1);
                } else if (epi == EPI_GELU_H) {
                    v0 = 0.5f * v0 * (1.0f + erff(v0 * 0.70710678118654752f));
                    v1 = 0.5f * v1 * (1.0f + erff(v1 * 0.70710678118654752f));
                    *(__half2*)(Ch + (size_t)r * N + col) = __floats2half2_rn(v0, v1);
                } else {
                    *(float2*)(C + (size_t)r * N + col) = make_float2(v0, v1);
                }
            }
        }
    }
}

// =================================================================
//  windowed attention on tensor cores (tf32 mma), fp16 output
// =================================================================
#define SW 324   // Ss row pitch (floats); 320 scores per row

__global__ void __launch_bounds__(256)
attn_tc_kernel(const float* __restrict__ qkv, __half* __restrict__ attn)
{
    const int qt = blockIdx.x;
    const int h  = blockIdx.y;
    const int b  = blockIdx.z;
    const int q0 = qt * 64;
    const int j0 = q0 - HALF_WIN;

    extern __shared__ float sm[];
    float* Qs = sm;                  // [64][68]
    float* Ks = Qs + 64 * 68;        // [64][68]
    float* Vt = Ks + 64 * 68;        // [64 d][68 j]
    float* Ss = Vt + 64 * 68;        // [64][SW]

    const int tid = threadIdx.x;
    const int lane = tid & 31, warp = tid >> 5;
    const int mw = warp & 3, nw = warp >> 2;
    const int lr = lane >> 2, lc = lane & 3;

    const size_t base = (size_t)(b * SEQ_L) * 3072 + (size_t)h * 64;

    for (int idx = tid; idx < 64 * 64; idx += 256) {
        int r = idx >> 6, c = idx & 63;
        Qs[r * 68 + c] = qkv[base + (size_t)(q0 + r) * 3072 + c] * 0.125f;
    }

    for (int t = 0; t < 5; ++t) {
        int jb = j0 + t * 64;
        __syncthreads();
        for (int idx = tid; idx < 64 * 64; idx += 256) {
            int r = idx >> 6, c = idx & 63;
            int j = jb + r; j = min(max(j, 0), SEQ_L - 1);
            Ks[r * 68 + c] = qkv[base + (size_t)j * 3072 + 1024 + c];
        }
        __syncthreads();

        float acc[4][4];
        #pragma unroll
        for (int nt = 0; nt < 4; nt++)
            #pragma unroll
            for (int e = 0; e < 4; e++) acc[nt][e] = 0.f;

        #pragma unroll
        for (int k8 = 0; k8 < 8; ++k8) {
            const float* ap = Qs + (mw * 16 + lr) * 68 + k8 * 8 + lc;
            uint32_t af[4];
            af[0] = __float_as_uint(ap[0]);
            af[1] = __float_as_uint(ap[8 * 68]);
            af[2] = __float_as_uint(ap[4]);
            af[3] = __float_as_uint(ap[8 * 68 + 4]);
            #pragma unroll
            for (int nt = 0; nt < 4; ++nt) {
                const float* bp = Ks + (nw * 32 + nt * 8 + lr) * 68 + k8 * 8 + lc;
                uint32_t bf[2];
                bf[0] = __float_as_uint(bp[0]);
                bf[1] = __float_as_uint(bp[4]);
                mma_tf32(acc[nt], af, bf);
            }
        }

        #pragma unroll
        for (int nt = 0; nt < 4; ++nt) {
            #pragma unroll
            for (int e = 0; e < 4; ++e) {
                int rl = mw * 16 + lr + (e >> 1) * 8;
                int cl = t * 64 + nw * 32 + nt * 8 + 2 * lc + (e & 1);
                int j  = j0 + cl;
                int dd = cl - rl - HALF_WIN;
                bool ok = (j >= 0) && (j < SEQ_L) && (dd >= -HALF_WIN) && (dd <= HALF_WIN);
                Ss[rl * SW + cl] = ok ? acc[nt][e] : -INFINITY;
            }
        }
    }
    __syncthreads();

    for (int r = warp; r < 64; r += 8) {
        float* row = Ss + r * SW;
        float m = -INFINITY;
        #pragma unroll
        for (int k = 0; k < 10; ++k) m = fmaxf(m, row[lane + k * 32]);
        m = warp_max(m);
        float s = 0.f;
        #pragma unroll
        for (int k = 0; k < 10; ++k) {
            float e = __expf(row[lane + k * 32] - m);
            row[lane + k * 32] = e;
            s += e;
        }
        s = warp_sum(s);
        float inv = 1.f / s;
        #pragma unroll
        for (int k = 0; k < 10; ++k) row[lane + k * 32] *= inv;
    }

    float oacc[4][4];
    #pragma unroll
    for (int nt = 0; nt < 4; nt++)
        #pragma unroll
        for (int e = 0; e < 4; e++) oacc[nt][e] = 0.f;

    for (int t = 0; t < 5; ++t) {
        int jb = j0 + t * 64;
        __syncthreads();
        for (int idx = tid; idx < 64 * 64; idx += 256) {
            int r = idx >> 6, c = idx & 63;
            int j = jb + r; j = min(max(j, 0), SEQ_L - 1);
            Vt[c * 68 + r] = qkv[base + (size_t)j * 3072 + 2048 + c];
        }
        __syncthreads();

        #pragma unroll
        for (int k8 = 0; k8 < 8; ++k8) {
            const float* ap = Ss + (mw * 16 + lr) * SW + t * 64 + k8 * 8 + lc;
            uint32_t af[4];
            af[0] = __float_as_uint(ap[0]);
            af[1] = __float_as_uint(ap[8 * SW]);
            af[2] = __float_as_uint(ap[4]);
            af[3] = __float_as_uint(ap[8 * SW + 4]);
            #pragma unroll
            for (int nt = 0; nt < 4; ++nt) {
                const float* bp = Vt + (nw * 32 + nt * 8 + lr) * 68 + k8 * 8 + lc;
                uint32_t bf[2];
                bf[0] = __float_as_uint(bp[0]);
                bf[1] = __float_as_uint(bp[4]);
                mma_tf32(oacc[nt], af, bf);
            }
        }
    }

    #pragma unroll
    for (int nt = 0; nt < 4; ++nt) {
        int col = h * 64 + nw * 32 + nt * 8 + 2 * lc;
        #pragma unroll
        for (int half_ = 0; half_ < 2; ++half_) {
            int r = q0 + mw * 16 + lr + half_ * 8;
            *(__half2*)(attn + (size_t)(b * SEQ_L + r) * D_MODEL + col)
                = __floats2half2_rn(oacc[nt][half_ * 2], oacc[nt][half_ * 2 + 1]);
        }
    }
}

#define ATTN_SMEM ((3 * 64 * 68 + 64 * SW) * sizeof(float))   // 135168 B

// ---------------- launch ----------------
extern "C" void kernel_launch(void* const* d_in, const int* in_sizes, int n_in,
                              void* d_out, int out_size)
{
    const float* x      = (const float*)d_in[0];
    const float* qkv_w  = (const float*)d_in[1];
    const float* qkv_b  = (const float*)d_in[2];
    const float* out_w  = (const float*)d_in[3];
    const float* out_b  = (const float*)d_in[4];
    const float* ln1_g  = (const float*)d_in[5];
    const float* ln1_b  = (const float*)d_in[6];
    const float* ln2_g  = (const float*)d_in[7];
    const float* ln2_b  = (const float*)d_in[8];
    const float* ffn_w1 = (const float*)d_in[9];
    const float* ffn_b1 = (const float*)d_in[10];
    const float* ffn_w2 = (const float*)d_in[11];
    const float* ffn_b2 = (const float*)d_in[12];
    float* out = (float*)d_out;

    float *qkv, *x1;
    __half *h16, *att16, *ff16, *wq16, *wo16, *w116, *w216;
    cudaGetSymbolAddress((void**)&qkv,  g_qkv);
    cudaGetSymbolAddress((void**)&x1,   g_x1);
    cudaGetSymbolAddress((void**)&h16,  g_h16);
    cudaGetSymbolAddress((void**)&att16,g_att16);
    cudaGetSymbolAddress((void**)&ff16, g_ff16);
    cudaGetSymbolAddress((void**)&wq16, g_wq16);
    cudaGetSymbolAddress((void**)&wo16, g_wo16);
    cudaGetSymbolAddress((void**)&w116, g_w116);
    cudaGetSymbolAddress((void**)&w216, g_w216);

    cudaFuncSetAttribute(attn_tc_kernel, cudaFuncAttributeMaxDynamicSharedMemorySize, (int)ATTN_SMEM);
    cudaFuncSetAttribute(gemm_h_kernel,  cudaFuncAttributeMaxDynamicSharedMemorySize, (int)GEMM_SMEM);

    // 0) weight conversions fp32->fp16
    {
        int n4;
        n4 = D_MODEL * 3 * D_MODEL / 4;
        f2h_kernel<<<(n4 + 255) / 256, 256>>>((const float4*)qkv_w, (__half2*)wq16, n4);
        n4 = D_MODEL * D_MODEL / 4;
        f2h_kernel<<<(n4 + 255) / 256, 256>>>((const float4*)out_w, (__half2*)wo16, n4);
        n4 = D_MODEL * 2 * D_MODEL / 4;
        f2h_kernel<<<(n4 + 255) / 256, 256>>>((const float4*)ffn_w1, (__half2*)w116, n4);
        n4 = 2 * D_MODEL * D_MODEL / 4;
        f2h_kernel<<<(n4 + 255) / 256, 256>>>((const float4*)ffn_w2, (__half2*)w216, n4);
    }

    // 1) LN1 -> fp16
    ln_kernel<<<NTOK, 256>>>(x, ln1_g, ln1_b, h16);
    // 2) QKV projection (fp16 TC, fp32 out)
    gemm_h_kernel<<<dim3(3 * D_MODEL / 128, NTOK / 128), 256, GEMM_SMEM>>>(
        h16, wq16, qkv_b, nullptr, qkv, nullptr, NTOK, 3 * D_MODEL, D_MODEL, EPI_BIAS);
    // 3) windowed attention (tf32 TC, fp16 out)
    attn_tc_kernel<<<dim3(SEQ_L / 64, N_HEADS, BATCH), 256, ATTN_SMEM>>>(qkv, att16);
    // 4) output projection + residual (fp16 TC, fp32 out)
    gemm_h_kernel<<<dim3(D_MODEL / 128, NTOK / 128), 256, GEMM_SMEM>>>(
        att16, wo16, out_b, x, x1, nullptr, NTOK, D_MODEL, D_MODEL, EPI_BIAS_RES);
    // 5) LN2 -> fp16
    ln_kernel<<<NTOK, 256>>>(x1, ln2_g, ln2_b, h16);
    // 6) FFN1 + GELU (fp16 TC, fp16 out)
    gemm_h_kernel<<<dim3(2 * D_MODEL / 128, NTOK / 128), 256, GEMM_SMEM>>>(
        h16, w116, ffn_b1, nullptr, nullptr, ff16, NTOK, 2 * D_MODEL, D_MODEL, EPI_GELU_H);
    // 7) FFN2 + residual -> out (fp16 TC, fp32 out)
    gemm_h_kernel<<<dim3(D_MODEL / 128, NTOK / 128), 256, GEMM_SMEM>>>(
        ff16, w216, ffn_b2, x1, out, nullptr, NTOK, D_MODEL, 2 * D_MODEL, EPI_BIAS_RES);
}

// round 7
// speedup vs baseline: 5.8927x; 1.2840x over previous
#include <cuda_runtime.h>
#include <cuda_fp16.h>
#include <math.h>
#include <stdint.h>

#define D_MODEL   1024
#define N_HEADS   16
#define HEAD_DIM  64
#define SEQ_L     2048
#define BATCH     2
#define NTOK      (BATCH * SEQ_L)      // 4096
#define HALF_WIN  128                  // WINDOW//2
#define LN_EPS    1e-5f

// ---------------- scratch (no allocation allowed) ----------------
__device__ float  g_x1 [NTOK * D_MODEL];        // x + attn_out (fp32)
__device__ __half g_qkvh[NTOK * 3 * D_MODEL];   // qkv projection (fp16)
__device__ __half g_h16 [NTOK * D_MODEL];       // LN1 out, then reused for LN2 out
__device__ __half g_att16[NTOK * D_MODEL];      // attention output (fp16)
__device__ __half g_ff16 [NTOK * 2 * D_MODEL];  // gelu(ffn1) (fp16)
__device__ __half g_wq16 [D_MODEL * 3 * D_MODEL];
__device__ __half g_wo16 [D_MODEL * D_MODEL];
__device__ __half g_w116 [D_MODEL * 2 * D_MODEL];
__device__ __half g_w216 [2 * D_MODEL * D_MODEL];

// ---------------- helpers ----------------
__inline__ __device__ float warp_sum(float v) {
    #pragma unroll
    for (int o = 16; o > 0; o >>= 1) v += __shfl_xor_sync(0xffffffffu, v, o);
    return v;
}
__inline__ __device__ float warp_max(float v) {
    #pragma unroll
    for (int o = 16; o > 0; o >>= 1) v = fmaxf(v, __shfl_xor_sync(0xffffffffu, v, o));
    return v;
}

__device__ __forceinline__ void cp16(void* smem_dst, const void* gmem_src) {
    uint32_t s = (uint32_t)__cvta_generic_to_shared(smem_dst);
    asm volatile("cp.async.cg.shared.global [%0], [%1], 16;\n" :: "r"(s), "l"(gmem_src));
}
__device__ __forceinline__ void cp_commit() { asm volatile("cp.async.commit_group;\n"); }
__device__ __forceinline__ void cp_wait1()  { asm volatile("cp.async.wait_group 1;\n"); }

__device__ __forceinline__ void mma_f16(float* c, const uint32_t* a, const uint32_t* b) {
    asm volatile(
        "mma.sync.aligned.m16n8k16.row.col.f32.f16.f16.f32 "
        "{%0,%1,%2,%3}, {%4,%5,%6,%7}, {%8,%9}, {%0,%1,%2,%3};\n"
        : "+f"(c[0]), "+f"(c[1]), "+f"(c[2]), "+f"(c[3])
        : "r"(a[0]), "r"(a[1]), "r"(a[2]), "r"(a[3]), "r"(b[0]), "r"(b[1]));
}
__device__ __forceinline__ void ldmx4(uint32_t& r0, uint32_t& r1, uint32_t& r2, uint32_t& r3, uint32_t addr) {
    asm volatile("ldmatrix.sync.aligned.m8n8.x4.shared.b16 {%0,%1,%2,%3}, [%4];\n"
                 : "=r"(r0), "=r"(r1), "=r"(r2), "=r"(r3) : "r"(addr));
}
__device__ __forceinline__ void ldmx4t(uint32_t& r0, uint32_t& r1, uint32_t& r2, uint32_t& r3, uint32_t addr) {
    asm volatile("ldmatrix.sync.aligned.m8n8.x4.trans.shared.b16 {%0,%1,%2,%3}, [%4];\n"
                 : "=r"(r0), "=r"(r1), "=r"(r2), "=r"(r3) : "r"(addr));
}

// ---------------- fp32 -> fp16 conversion (weights) ----------------
__global__ void __launch_bounds__(256)
f2h_kernel(const float4* __restrict__ in, __half2* __restrict__ out, int n4)
{
    int i = blockIdx.x * 256 + threadIdx.x;
    if (i < n4) {
        float4 v = in[i];
        out[2 * i]     = __floats2half2_rn(v.x, v.y);
        out[2 * i + 1] = __floats2half2_rn(v.z, v.w);
    }
}

// ---------------- LayerNorm: one block per token, fp16 output ----------------
__global__ void __launch_bounds__(256)
ln_kernel(const float* __restrict__ x, const float* __restrict__ g,
          const float* __restrict__ b, __half* __restrict__ out)
{
    int row = blockIdx.x;
    const float* xr = x + (size_t)row * D_MODEL;
    __half*      orow = out + (size_t)row * D_MODEL;
    int tid = threadIdx.x;

    float v[4];
    float s = 0.f, ss = 0.f;
    #pragma unroll
    for (int i = 0; i < 4; i++) {
        v[i] = xr[tid + i * 256];
        s  += v[i];
        ss += v[i] * v[i];
    }
    __shared__ float shs[8], shss[8], fin[2];
    int lane = tid & 31, warp = tid >> 5;
    s = warp_sum(s); ss = warp_sum(ss);
    if (lane == 0) { shs[warp] = s; shss[warp] = ss; }
    __syncthreads();
    if (tid == 0) {
        float a = 0.f, c = 0.f;
        #pragma unroll
        for (int i = 0; i < 8; i++) { a += shs[i]; c += shss[i]; }
        fin[0] = a; fin[1] = c;
    }
    __syncthreads();
    float mu  = fin[0] * (1.f / D_MODEL);
    float var = fin[1] * (1.f / D_MODEL) - mu * mu;
    float inv = rsqrtf(var + LN_EPS);
    #pragma unroll
    for (int i = 0; i < 4; i++) {
        int c = tid + i * 256;
        orow[c] = __float2half_rn((v[i] - mu) * inv * g[c] + b[c]);
    }
}

// =================================================================
//  fp16 tensor-core GEMM (as R5) + fp16-output bias epilogue
// =================================================================
#define EPI_BIAS     0
#define EPI_BIAS_RES 1
#define EPI_GELU_H   2
#define EPI_BIAS_H   3

#define AP16 40
#define BP16 136
#define HASZ (128 * AP16)
#define HBSZ (32  * BP16)
#define STAGES 3
#define GEMM_SMEM ((size_t)STAGES * (HASZ + HBSZ) * sizeof(__half))   // 56832 B

__global__ void __launch_bounds__(256)
gemm_h_kernel(const __half* __restrict__ A, const __half* __restrict__ Bm,
              const float* __restrict__ bias, const float* __restrict__ res,
              float* __restrict__ C, __half* __restrict__ Ch,
              int M, int N, int K, int epi)
{
    extern __shared__ __half hsm[];
    __half* As = hsm;
    __half* Bs = hsm + STAGES * HASZ;
    uint32_t smem_u = (uint32_t)__cvta_generic_to_shared(hsm);

    int tid  = threadIdx.x;
    int lane = tid & 31;
    int warp = tid >> 5;
    int warp_m = (warp & 3) * 32;
    int warp_n = (warp >> 2) * 64;
    int bm = blockIdx.y * 128;
    int bn = blockIdx.x * 128;

    const int kIters = K >> 5;

    auto load_tile = [&](int it, int buf) {
        int k0 = it << 5;
        __half* Ab = As + buf * HASZ;
        __half* Bb = Bs + buf * HBSZ;
        #pragma unroll
        for (int t = 0; t < 2; t++) {
            int idx = tid + t * 256;
            int m  = idx >> 2;
            int c8 = (idx & 3) << 3;
            cp16(Ab + m * AP16 + c8, A + (size_t)(bm + m) * K + k0 + c8);
        }
        #pragma unroll
        for (int t = 0; t < 2; t++) {
            int idx = tid + t * 256;
            int k  = idx >> 4;
            int n8 = (idx & 15) << 3;
            cp16(Bb + k * BP16 + n8, Bm + (size_t)(k0 + k) * N + bn + n8);
        }
    };

    float acc[2][8][4];
    #pragma unroll
    for (int mt = 0; mt < 2; mt++)
        #pragma unroll
        for (int nt = 0; nt < 8; nt++)
            #pragma unroll
            for (int i = 0; i < 4; i++) acc[mt][nt][i] = 0.f;

    int a_row = warp_m + (lane & 15);
    int a_c8  = (lane >> 4) << 3;
    int b_k   = lane & 15;
    int b_c8  = (lane >> 4) << 3;

    load_tile(0, 0); cp_commit();
    load_tile(1, 1); cp_commit();

    int cur = 0;
    for (int it = 0; it < kIters; ++it) {
        cp_wait1();
        __syncthreads();
        if (it + 2 < kIters) {
            int buf = cur + 2; if (buf >= STAGES) buf -= STAGES;
            load_tile(it + 2, buf);
        }
        cp_commit();

        uint32_t Abase = smem_u + (uint32_t)(cur * HASZ) * 2;
        uint32_t Bbase = smem_u + (uint32_t)(STAGES * HASZ + cur * HBSZ) * 2;

        #pragma unroll
        for (int kk = 0; kk < 2; ++kk) {
            uint32_t af[2][4], bf[8][2];
            #pragma unroll
            for (int mt = 0; mt < 2; mt++) {
                uint32_t addr = Abase + ((a_row + mt * 16) * AP16 + kk * 16 + a_c8) * 2;
                ldmx4(af[mt][0], af[mt][1], af[mt][2], af[mt][3], addr);
            }
            #pragma unroll
            for (int np = 0; np < 4; np++) {
                uint32_t addr = Bbase + ((kk * 16 + b_k) * BP16 + warp_n + np * 16 + b_c8) * 2;
                ldmx4t(bf[2 * np][0], bf[2 * np][1], bf[2 * np + 1][0], bf[2 * np + 1][1], addr);
            }
            #pragma unroll
            for (int mt = 0; mt < 2; mt++)
                #pragma unroll
                for (int nt = 0; nt < 8; nt++)
                    mma_f16(acc[mt][nt], af[mt], bf[nt]);
        }
        cur = cur + 1; if (cur >= STAGES) cur -= STAGES;
    }

    // ---------------- epilogue ----------------
    #pragma unroll
    for (int mt = 0; mt < 2; mt++) {
        int row0 = bm + warp_m + mt * 16 + (lane >> 2);
        #pragma unroll
        for (int nt = 0; nt < 8; nt++) {
            int col = bn + warp_n + nt * 8 + (lane & 3) * 2;
            float b0 = bias[col], b1 = bias[col + 1];
            #pragma unroll
            for (int half_ = 0; half_ < 2; half_++) {
                int r = row0 + half_ * 8;
                float v0 = acc[mt][nt][half_ * 2 + 0] + b0;
                float v1 = acc[mt][nt][half_ * 2 + 1] + b1;
                if (epi == EPI_BIAS_RES) {
                    const float* rr = res + (size_t)r * N;
                    v0 += rr[col]; v1 += rr[col + 1];
                    *(float2*)(C + (size_t)r * N + col) = make_float2(v0, v1);
                } else if (epi == EPI_GELU_H) {
                    v0 = 0.5f * v0 * (1.0f + erff(v0 * 0.70710678118654752f));
                    v1 = 0.5f * v1 * (1.0f + erff(v1 * 0.70710678118654752f));
                    *(__half2*)(Ch + (size_t)r * N + col) = __floats2half2_rn(v0, v1);
                } else if (epi == EPI_BIAS_H) {
                    *(__half2*)(Ch + (size_t)r * N + col) = __floats2half2_rn(v0, v1);
                } else {
                    *(float2*)(C + (size_t)r * N + col) = make_float2(v0, v1);
                }
            }
        }
    }
}

// =================================================================
//  windowed attention, fully fp16 tensor-core path
//  grid (L/64, H, B), 256 threads (8 warps: mw=warp&3 16 rows, nw=warp>>2 32 cols)
//  smem: Ss fp32 [64][324], Qh [64][72], KVh [64][72] (K then V), Ph [64][328]
// =================================================================
#define QP  72    // Q/K/V smem pitch in halves (144B -> 4-bank row stride)
#define SWF 324   // fp32 score pitch
#define SWH 328   // fp16 P pitch (656B -> 4-bank row stride)
#define ATTN_SMEM (64 * SWF * 4 + 2 * (64 * QP * 2) + 64 * SWH * 2)  // 143360 B

__global__ void __launch_bounds__(256)
attn_h_kernel(const __half* __restrict__ qkv, __half* __restrict__ attn)
{
    const int qt = blockIdx.x;
    const int h  = blockIdx.y;
    const int b  = blockIdx.z;
    const int q0 = qt * 64;
    const int j0 = q0 - HALF_WIN;

    extern __shared__ char asmem[];
    float*  Ss = (float*)asmem;                       // [64][SWF]
    __half* Qh = (__half*)(asmem + 64 * SWF * 4);     // [64][QP]
    __half* KV = Qh + 64 * QP;                        // [64][QP]
    __half* Ph = KV + 64 * QP;                        // [64][SWH]
    uint32_t su  = (uint32_t)__cvta_generic_to_shared(asmem);
    uint32_t Qu  = su + 64 * SWF * 4;
    uint32_t KVu = Qu + 64 * QP * 2;
    uint32_t Pu  = KVu + 64 * QP * 2;

    const int tid = threadIdx.x;
    const int lane = tid & 31, warp = tid >> 5;
    const int mw = warp & 3, nw = warp >> 2;
    const int lr = lane >> 2, lc = lane & 3;
    const int l15 = lane & 15;
    const int lhi8 = (lane >> 4) << 3;

    const size_t base = (size_t)(b * SEQ_L) * 3072 + (size_t)h * 64;

    // ---- load Q tile (fp16, vectorized) ----
    #pragma unroll
    for (int t = 0; t < 2; ++t) {
        int idx = tid + t * 256;
        int r = idx >> 3, c8 = (idx & 7) << 3;
        *(uint4*)(Qh + r * QP + c8) = *(const uint4*)(qkv + base + (size_t)(q0 + r) * 3072 + c8);
    }

    // ---- S = (Q @ K^T) * scale, masked into Ss ----
    for (int t = 0; t < 5; ++t) {
        int jb = j0 + t * 64;
        __syncthreads();
        #pragma unroll
        for (int tt = 0; tt < 2; ++tt) {
            int idx = tid + tt * 256;
            int r = idx >> 3, c8 = (idx & 7) << 3;
            int j = jb + r; j = min(max(j, 0), SEQ_L - 1);
            *(uint4*)(KV + r * QP + c8) = *(const uint4*)(qkv + base + (size_t)j * 3072 + 1024 + c8);
        }
        __syncthreads();

        float acc[4][4];
        #pragma unroll
        for (int nt = 0; nt < 4; nt++)
            #pragma unroll
            for (int e = 0; e < 4; e++) acc[nt][e] = 0.f;

        #pragma unroll
        for (int kk = 0; kk < 4; ++kk) {
            uint32_t af[4];
            ldmx4(af[0], af[1], af[2], af[3],
                  Qu + ((mw * 16 + l15) * QP + kk * 16 + lhi8) * 2);
            uint32_t bf[4][2];
            #pragma unroll
            for (int np = 0; np < 2; ++np) {
                uint32_t r0, r1, r2, r3;
                ldmx4(r0, r1, r2, r3,
                      KVu + ((nw * 32 + np * 16 + l15) * QP + kk * 16 + lhi8) * 2);
                bf[2 * np][0] = r0; bf[2 * np][1] = r2;
                bf[2 * np + 1][0] = r1; bf[2 * np + 1][1] = r3;
            }
            #pragma unroll
            for (int nt = 0; nt < 4; ++nt) mma_f16(acc[nt], af, bf[nt]);
        }

        #pragma unroll
        for (int nt = 0; nt < 4; ++nt) {
            #pragma unroll
            for (int e = 0; e < 4; ++e) {
                int rl = mw * 16 + lr + (e >> 1) * 8;
                int cl = t * 64 + nw * 32 + nt * 8 + 2 * lc + (e & 1);
                int j  = j0 + cl;
                int dd = cl - rl - HALF_WIN;                 // j - i
                bool ok = (j >= 0) && (j < SEQ_L) && (dd >= -HALF_WIN) && (dd <= HALF_WIN);
                Ss[rl * SWF + cl] = ok ? acc[nt][e] * 0.125f : -INFINITY;
            }
        }
    }
    __syncthreads();

    // ---- softmax per row (fp32) -> P fp16 ----
    for (int r = warp; r < 64; r += 8) {
        const float* row = Ss + r * SWF;
        __half* prow = Ph + r * SWH;
        float m = -INFINITY;
        float vv[10];
        #pragma unroll
        for (int k = 0; k < 10; ++k) { vv[k] = row[lane + k * 32]; m = fmaxf(m, vv[k]); }
        m = warp_max(m);
        float s = 0.f;
        #pragma unroll
        for (int k = 0; k < 10; ++k) { vv[k] = __expf(vv[k] - m); s += vv[k]; }
        s = warp_sum(s);
        float inv = 1.f / s;
        #pragma unroll
        for (int k = 0; k < 10; ++k) prow[lane + k * 32] = __float2half_rn(vv[k] * inv);
    }

    // ---- O = P @ V ----
    float oacc[4][4];
    #pragma unroll
    for (int nt = 0; nt < 4; nt++)
        #pragma unroll
        for (int e = 0; e < 4; e++) oacc[nt][e] = 0.f;

    for (int t = 0; t < 5; ++t) {
        int jb = j0 + t * 64;
        __syncthreads();
        #pragma unroll
        for (int tt = 0; tt < 2; ++tt) {
            int idx = tid + tt * 256;
            int r = idx >> 3, c8 = (idx & 7) << 3;
            int j = jb + r; j = min(max(j, 0), SEQ_L - 1);
            *(uint4*)(KV + r * QP + c8) = *(const uint4*)(qkv + base + (size_t)j * 3072 + 2048 + c8);
        }
        __syncthreads();

        #pragma unroll
        for (int kk = 0; kk < 4; ++kk) {
            uint32_t af[4];
            ldmx4(af[0], af[1], af[2], af[3],
                  Pu + ((mw * 16 + l15) * SWH + t * 64 + kk * 16 + lhi8) * 2);
            uint32_t bf[4][2];
            #pragma unroll
            for (int np = 0; np < 2; ++np) {
                // V stored [j][d] row-major -> trans ldmatrix gives B frags (n=d, k=j)
                ldmx4t(bf[2 * np][0], bf[2 * np][1], bf[2 * np + 1][0], bf[2 * np + 1][1],
                       KVu + ((kk * 16 + l15) * QP + nw * 32 + np * 16 + lhi8) * 2);
            }
            #pragma unroll
            for (int nt = 0; nt < 4; ++nt) mma_f16(oacc[nt], af, bf[nt]);
        }
    }

    // ---- write O (fp16, token-major head slice) ----
    #pragma unroll
    for (int nt = 0; nt < 4; ++nt) {
        int col = h * 64 + nw * 32 + nt * 8 + 2 * lc;
        #pragma unroll
        for (int half_ = 0; half_ < 2; ++half_) {
            int r = q0 + mw * 16 + lr + half_ * 8;
            *(__half2*)(attn + (size_t)(b * SEQ_L + r) * D_MODEL + col)
                = __floats2half2_rn(oacc[nt][half_ * 2], oacc[nt][half_ * 2 + 1]);
        }
    }
}

// ---------------- launch ----------------
extern "C" void kernel_launch(void* const* d_in, const int* in_sizes, int n_in,
                              void* d_out, int out_size)
{
    const float* x      = (const float*)d_in[0];
    const float* qkv_w  = (const float*)d_in[1];
    const float* qkv_b  = (const float*)d_in[2];
    const float* out_w  = (const float*)d_in[3];
    const float* out_b  = (const float*)d_in[4];
    const float* ln1_g  = (const float*)d_in[5];
    const float* ln1_b  = (const float*)d_in[6];
    const float* ln2_g  = (const float*)d_in[7];
    const float* ln2_b  = (const float*)d_in[8];
    const float* ffn_w1 = (const float*)d_in[9];
    const float* ffn_b1 = (const float*)d_in[10];
    const float* ffn_w2 = (const float*)d_in[11];
    const float* ffn_b2 = (const float*)d_in[12];
    float* out = (float*)d_out;

    float *x1;
    __half *qkvh, *h16, *att16, *ff16, *wq16, *wo16, *w116, *w216;
    cudaGetSymbolAddress((void**)&x1,   g_x1);
    cudaGetSymbolAddress((void**)&qkvh, g_qkvh);
    cudaGetSymbolAddress((void**)&h16,  g_h16);
    cudaGetSymbolAddress((void**)&att16,g_att16);
    cudaGetSymbolAddress((void**)&ff16, g_ff16);
    cudaGetSymbolAddress((void**)&wq16, g_wq16);
    cudaGetSymbolAddress((void**)&wo16, g_wo16);
    cudaGetSymbolAddress((void**)&w116, g_w116);
    cudaGetSymbolAddress((void**)&w216, g_w216);

    cudaFuncSetAttribute(attn_h_kernel, cudaFuncAttributeMaxDynamicSharedMemorySize, (int)ATTN_SMEM);
    cudaFuncSetAttribute(gemm_h_kernel, cudaFuncAttributeMaxDynamicSharedMemorySize, (int)GEMM_SMEM);

    // 0) weight conversions fp32->fp16
    {
        int n4;
        n4 = D_MODEL * 3 * D_MODEL / 4;
        f2h_kernel<<<(n4 + 255) / 256, 256>>>((const float4*)qkv_w, (__half2*)wq16, n4);
        n4 = D_MODEL * D_MODEL / 4;
        f2h_kernel<<<(n4 + 255) / 256, 256>>>((const float4*)out_w, (__half2*)wo16, n4);
        n4 = D_MODEL * 2 * D_MODEL / 4;
        f2h_kernel<<<(n4 + 255) / 256, 256>>>((const float4*)ffn_w1, (__half2*)w116, n4);
        n4 = 2 * D_MODEL * D_MODEL / 4;
        f2h_kernel<<<(n4 + 255) / 256, 256>>>((const float4*)ffn_w2, (__half2*)w216, n4);
    }

    // 1) LN1 -> fp16
    ln_kernel<<<NTOK, 256>>>(x, ln1_g, ln1_b, h16);
    // 2) QKV projection (fp16 TC, fp16 out)
    gemm_h_kernel<<<dim3(3 * D_MODEL / 128, NTOK / 128), 256, GEMM_SMEM>>>(
        h16, wq16, qkv_b, nullptr, nullptr, qkvh, NTOK, 3 * D_MODEL, D_MODEL, EPI_BIAS_H);
    // 3) windowed attention (fp16 TC)
    attn_h_kernel<<<dim3(SEQ_L / 64, N_HEADS, BATCH), 256, ATTN_SMEM>>>(qkvh, att16);
    // 4) output projection + residual (fp16 TC, fp32 out)
    gemm_h_kernel<<<dim3(D_MODEL / 128, NTOK / 128), 256, GEMM_SMEM>>>(
        att16, wo16, out_b, x, x1, nullptr, NTOK, D_MODEL, D_MODEL, EPI_BIAS_RES);
    // 5) LN2 -> fp16
    ln_kernel<<<NTOK, 256>>>(x1, ln2_g, ln2_b, h16);
    // 6) FFN1 + GELU (fp16 TC, fp16 out)
    gemm_h_kernel<<<dim3(2 * D_MODEL / 128, NTOK / 128), 256, GEMM_SMEM>>>(
        h16, w116, ffn_b1, nullptr, nullptr, ff16, NTOK, 2 * D_MODEL, D_MODEL, EPI_GELU_H);
    // 7) FFN2 + residual -> out (fp16 TC, fp32 out)
    gemm_h_kernel<<<dim3(D_MODEL / 128, NTOK / 128), 256, GEMM_SMEM>>>(
        ff16, w216, ffn_b2, x1, out, nullptr, NTOK, D_MODEL, 2 * D_MODEL, EPI_BIAS_RES);
}